// round 11
// baseline (speedup 1.0000x reference)
#include <cuda_runtime.h>
#include <cuda_fp16.h>

#define N_NODES 16384
#define N_EDGES 262144
#define D_CH    256
#define BN_EPS  1e-5f

// ================= device scratch (no runtime allocation) ==================
__device__ __half g_x [N_NODES * D_CH];
__device__ __half g_e [N_NODES * D_CH];
__device__ __half g_e2[N_NODES * D_CH];
__device__ __half g_r [N_NODES * D_CH];
__device__ __half g_q [N_NODES * D_CH];

// fp16 copies of the edge-weight tables
__device__ __half g_ew1h[N_NODES * D_CH];
__device__ __half g_ew2h[N_NODES * D_CH];

// stacked split weights, layout [N=256 rows][K'=512]: [hi(256) | lo(256)]
__device__ __half g_Bw1a[D_CH * 512];
__device__ __half g_Bf1a[D_CH * 512];
__device__ __half g_Bw1b[D_CH * 512];
__device__ __half g_Bf1b[D_CH * 512];
__device__ __half g_Bwx [D_CH * 512];
__device__ __half g_B2  [D_CH * 512];
__device__ __half g_Bf2 [D_CH * 512];

__device__ float g_wx2[D_CH * D_CH];
__device__ float g_G  [D_CH * D_CH];

__device__ float g_biasr[D_CH];
__device__ float g_bias3[D_CH];

__device__ float g_sum1[D_CH];
__device__ float g_sq1 [D_CH];
__device__ float g_sum2[D_CH];
__device__ float g_sq2 [D_CH];

__device__ int g_deg[N_NODES];
__device__ int g_off[N_NODES + 1];
__device__ int g_cur[N_NODES];
__device__ int g_csr[N_EDGES];

// ================= PTX helpers (sm_100 BASE ISA only) =======================
__device__ __forceinline__ unsigned smem_u32(const void* p) {
    unsigned a;
    asm("{ .reg .u64 t; cvta.to.shared.u64 t, %1; cvt.u32.u64 %0, t; }"
        : "=r"(a) : "l"(p));
    return a;
}

__device__ __forceinline__ void cp16(unsigned dst, const void* src) {
    asm volatile("cp.async.cg.shared.global [%0], [%1], 16;"
                 :: "r"(dst), "l"(src) : "memory");
}
__device__ __forceinline__ void cp_commit() {
    asm volatile("cp.async.commit_group;" ::: "memory");
}
template <int N>
__device__ __forceinline__ void cp_wait() {
    asm volatile("cp.async.wait_group %0;" :: "n"(N) : "memory");
}

__device__ __forceinline__ void ldsm_x4(unsigned* r, unsigned addr) {
    asm volatile("ldmatrix.sync.aligned.m8n8.x4.shared.b16 {%0,%1,%2,%3}, [%4];"
                 : "=r"(r[0]), "=r"(r[1]), "=r"(r[2]), "=r"(r[3]) : "r"(addr));
}

__device__ __forceinline__ void mma_fp16(float* c, const unsigned* a, const unsigned* b) {
    asm volatile(
        "mma.sync.aligned.m16n8k16.row.col.f32.f16.f16.f32 "
        "{%0,%1,%2,%3}, {%4,%5,%6,%7}, {%8,%9}, {%0,%1,%2,%3};"
        : "+f"(c[0]), "+f"(c[1]), "+f"(c[2]), "+f"(c[3])
        : "r"(a[0]), "r"(a[1]), "r"(a[2]), "r"(a[3]), "r"(b[0]), "r"(b[1]));
}

__device__ __forceinline__ void split1h(float v, __half& h, __half& l) {
    h = __float2half_rn(v);
    l = __float2half_rn(v - __half2float(h));
}
__device__ __forceinline__ uint2 pack4h(float4 v) {
    __half2 a = __floats2half2_rn(v.x, v.y);
    __half2 b = __floats2half2_rn(v.z, v.w);
    uint2 r;
    r.x = *(unsigned*)&a;
    r.y = *(unsigned*)&b;
    return r;
}

// ===== conversions (x, ew1, ew2) + stats zero — branch A =====================
__global__ void conv_k(const float* __restrict__ x,
                       const float* __restrict__ ew1,
                       const float* __restrict__ ew2,
                       __half* __restrict__ xh) {
    int b = blockIdx.x;
    if (b < 4096) {
        int i = b * 256 + threadIdx.x;
        ((uint2*)xh)[i] = pack4h(((const float4*)x)[i]);
    } else if (b < 8192) {
        int i = (b - 4096) * 256 + threadIdx.x;
        ((uint2*)g_ew1h)[i] = pack4h(((const float4*)ew1)[i]);
    } else if (b < 12288) {
        int i = (b - 8192) * 256 + threadIdx.x;
        ((uint2*)g_ew2h)[i] = pack4h(((const float4*)ew2)[i]);
    } else {
        int j = threadIdx.x;
        g_sum1[j] = 0.f; g_sq1[j] = 0.f;
        g_sum2[j] = 0.f; g_sq2[j] = 0.f;
    }
}

// ================= CSR construction =========================================
__global__ void zero_deg_k() {
    g_deg[blockIdx.x * 256 + threadIdx.x] = 0;
}
__global__ void hist_k(const int* __restrict__ ei) {
    int e = blockIdx.x * 256 + threadIdx.x;
    if (e < N_EDGES) atomicAdd(&g_deg[ei[N_EDGES + e]], 1);
}
__global__ void scan_k() {   // also initializes g_cur
    __shared__ int s[1024];
    int t = threadIdx.x;
    int base = t * 16;
    int local[16];
    int sum = 0;
#pragma unroll
    for (int i = 0; i < 16; i++) { local[i] = g_deg[base + i]; sum += local[i]; }
    s[t] = sum;
    __syncthreads();
    for (int d = 1; d < 1024; d <<= 1) {
        int v = 0;
        if (t >= d) v = s[t - d];
        __syncthreads();
        if (t >= d) s[t] += v;
        __syncthreads();
    }
    int prefix = (t == 0) ? 0 : s[t - 1];
    int run = prefix;
#pragma unroll
    for (int i = 0; i < 16; i++) {
        g_off[base + i] = run;
        g_cur[base + i] = run;
        run += local[i];
    }
    if (t == 1023) g_off[N_NODES] = run;
}
__global__ void scatter_k(const int* __restrict__ ei) {
    int e = blockIdx.x * 256 + threadIdx.x;
    if (e < N_EDGES) {
        int d = ei[N_EDGES + e];
        int p = atomicAdd(&g_cur[d], 1);
        g_csr[p] = ei[e];
    }
}

// ================= SpMM single layer (fp16 gather) -> fp16 ==================
__global__ void spmm_k(const __half* __restrict__ ew, const float* __restrict__ eb,
                       __half* __restrict__ eo) {
    int node = blockIdx.x * 4 + (threadIdx.x >> 6);
    int c = threadIdx.x & 63;
    const uint2* ew4 = (const uint2*)ew;
    float4 acc = ((const float4*)eb)[c];
    int s = g_off[node];
    int e = g_off[node + 1];
    for (int k = s; k < e; k++) {
        int j = g_csr[k];
        uint2 v = ew4[j * 64 + c];
        float2 f0 = __half22float2(*(const __half2*)&v.x);
        float2 f1 = __half22float2(*(const __half2*)&v.y);
        acc.x += f0.x; acc.y += f0.y; acc.z += f1.x; acc.w += f1.y;
    }
    ((uint2*)eo)[node * 64 + c] = pack4h(acc);
}

// ================= small fp32 GEMM tile (64x64, reg double-buffer) ===========
template <bool ADD_A, bool SPLIT>
__device__ __forceinline__ void wx_tile(const float* __restrict__ A,
                                        const float* __restrict__ B,
                                        float* __restrict__ Cf,
                                        __half* __restrict__ Ch,
                                        int bm, int bn) {
    __shared__ float As[16][64];
    __shared__ float Bs[16][68];
    int tx = threadIdx.x & 15, ty = threadIdx.x >> 4;
    int r = threadIdx.x >> 2, c4 = (threadIdx.x & 3) * 4;
    int rb = threadIdx.x >> 4, cb = (threadIdx.x & 15) * 4;
    float acc[4][4] = {};
    float4 av = *(const float4*)(A + (bm + r) * 256 + c4);
    float4 bv = *(const float4*)(B + rb * 256 + bn + cb);
    for (int kt = 0; kt < 256; kt += 16) {
        As[c4 + 0][r] = av.x; As[c4 + 1][r] = av.y;
        As[c4 + 2][r] = av.z; As[c4 + 3][r] = av.w;
        *(float4*)&Bs[rb][cb] = bv;
        __syncthreads();
        if (kt < 240) {
            av = *(const float4*)(A + (bm + r) * 256 + kt + 16 + c4);
            bv = *(const float4*)(B + (kt + 16 + rb) * 256 + bn + cb);
        }
#pragma unroll
        for (int k = 0; k < 16; k++) {
            float a[4], b[4];
#pragma unroll
            for (int i = 0; i < 4; i++) a[i] = As[k][ty * 4 + i];
#pragma unroll
            for (int j = 0; j < 4; j++) b[j] = Bs[k][tx * 4 + j];
#pragma unroll
            for (int i = 0; i < 4; i++)
#pragma unroll
                for (int j = 0; j < 4; j++) acc[i][j] = fmaf(a[i], b[j], acc[i][j]);
        }
        __syncthreads();
    }
#pragma unroll
    for (int i = 0; i < 4; i++) {
        int k = bm + ty * 4 + i;
#pragma unroll
        for (int j = 0; j < 4; j++) {
            int n = bn + tx * 4 + j;
            float w = acc[i][j];
            if (ADD_A) w += A[k * 256 + n];
            if (SPLIT) {
                __half h, l;
                split1h(w, h, l);
                Ch[n * 512 + k]       = h;
                Ch[n * 512 + 256 + k] = l;
            } else {
                Cf[k * 256 + n] = w;
            }
        }
    }
}

__global__ void wx2_k(const float* __restrict__ nw2, const float* __restrict__ c2w2) {
    wx_tile<true, false>(nw2, c2w2, g_wx2, nullptr, blockIdx.y * 64, blockIdx.x * 64);
}
__global__ void wx_pair_k(const float* __restrict__ nw1, const float* __restrict__ c2w1,
                          const float* __restrict__ f2w1) {
    if (blockIdx.z == 0)
        wx_tile<true, true>(nw1, c2w1, nullptr, g_Bwx, blockIdx.y * 64, blockIdx.x * 64);
    else
        wx_tile<false, false>(f2w1, g_wx2, g_G, nullptr, blockIdx.y * 64, blockIdx.x * 64);
}

__global__ void splitw_all_k(const float* __restrict__ c1w1, const float* __restrict__ f1w1,
                             const float* __restrict__ c1w2, const float* __restrict__ f1w2,
                             const float* __restrict__ nb1, const float* __restrict__ c1b1,
                             const float* __restrict__ c2b1, const float* __restrict__ c2w1) {
    int b = blockIdx.x, n = threadIdx.x;
    if (b < 1024) {
        int sel = b >> 8, k = b & 255;
        const float* W = (sel == 0) ? c1w1 : (sel == 1) ? f1w1 : (sel == 2) ? c1w2 : f1w2;
        __half* B = (sel == 0) ? g_Bw1a : (sel == 1) ? g_Bf1a : (sel == 2) ? g_Bw1b : g_Bf1b;
        float w = W[(k << 8) + n];
        if ((sel == 0 || sel == 2) && k == n) w += 1.f;
        __half h, l;
        split1h(w, h, l);
        B[n * 512 + k]       = h;
        B[n * 512 + 256 + k] = l;
    } else {
        float s = c1b1[n] + c2b1[n] + nb1[n];
        for (int k = 0; k < 256; k++) s += nb1[k] * c2w1[k * 256 + n];
        g_biasr[n] = s;
    }
}

__global__ void bneff2_k(const float* __restrict__ g1, const float* __restrict__ b1,
                         const float* __restrict__ f2b1,
                         const float* __restrict__ nb2, const float* __restrict__ c1b2,
                         const float* __restrict__ c2b2, const float* __restrict__ c2w2) {
    const float inv_n = 1.f / (float)N_NODES;
    int n = threadIdx.x;
    int b = blockIdx.x;
    if (b < 256) {
        int k = b;
        float mu = g_sum1[k] * inv_n;
        float var = g_sq1[k] * inv_n - mu * mu;
        float sc = rsqrtf(var + BN_EPS) * g1[k];
        __half h, l;
        split1h(sc * g_G[(k << 8) + n], h, l);
        g_B2[n * 512 + k]       = h;
        g_B2[n * 512 + 256 + k] = l;
    } else {
        float s = c1b2[n] + c2b2[n] + nb2[n];
        for (int k = 0; k < 256; k++) {
            float mu = g_sum1[k] * inv_n;
            float var = g_sq1[k] * inv_n - mu * mu;
            float rs = rsqrtf(var + BN_EPS);
            float t1 = b1[k] - mu * rs * g1[k];
            s += nb2[k] * c2w2[k * 256 + n] + t1 * g_G[(k << 8) + n]
               + f2b1[k] * g_wx2[(k << 8) + n];
        }
        g_biasr[n] = s;
    }
}

__global__ void bnfold_k(const float* __restrict__ gamma, const float* __restrict__ beta,
                         const float* __restrict__ f2w, const float* __restrict__ f2b) {
    const float inv_n = 1.f / (float)N_NODES;
    int n = threadIdx.x;
    int b = blockIdx.x;
    if (b < 256) {
        int k = b;
        float mu = g_sum2[k] * inv_n;
        float var = g_sq2[k] * inv_n - mu * mu;
        float scale = rsqrtf(var + BN_EPS) * gamma[k];
        __half h, l;
        split1h(f2w[(k << 8) + n] * scale, h, l);
        g_Bf2[n * 512 + k]       = h;
        g_Bf2[n * 512 + 256 + k] = l;
    } else {
        float s = f2b[n];
        for (int k = 0; k < 256; k++) {
            float mu = g_sum2[k] * inv_n;
            float var = g_sq2[k] * inv_n - mu * mu;
            float rs = rsqrtf(var + BN_EPS);
            s += (beta[k] - mu * rs * gamma[k]) * f2w[(k << 8) + n];
        }
        g_bias3[n] = s;
    }
}

// ================= HMMA fp16 2-term GEMM =====================================
#define STAGES   3
#define BUF_SZ   32768
#define STATS_OFF (STAGES * BUF_SZ)
#define SMEM_MMA (STATS_OFF + 1024)

template <int MODE, bool F32S, bool HST, bool XCOPY>
__global__ void __launch_bounds__(256, 2)
gemm_mma(const __half* __restrict__ A, const __half* __restrict__ A2,
         const __half* __restrict__ Bb, const __half* __restrict__ B2b,
         const float* __restrict__ bias,
         float* __restrict__ outf, int ldout,
         __half* __restrict__ oh,
         float* __restrict__ sumP, float* __restrict__ sqP,
         const float* __restrict__ xsrc) {
    extern __shared__ char smem[];
    const unsigned sbase = smem_u32(smem);
    const int tid = threadIdx.x;
    const int lane = tid & 31;
    const int w = tid >> 5;
    const int wm = w & 3;
    const int wn = w >> 2;
    const int bm = blockIdx.y * 128;
    const int bn = blockIdx.x * 128;

    const int NC = (MODE == 1) ? 16 : 8;

    auto issue = [&](int c) {
        const bool second = (MODE == 1) && (c >= 8);
        const int local = second ? c - 8 : c;
        const __half* Ap = second ? A2 : A;
        const __half* Bp = second ? B2b : Bb;
        const int ka = (local & 3) << 6;
        const int kb = local << 6;
        const unsigned sa = sbase + (c % STAGES) * BUF_SZ;
        const unsigned sb = sa + 16384;
#pragma unroll
        for (int i = 0; i < 4; i++) {
            int u = tid + (i << 8);
            int row = u >> 3, seg = u & 7;
            cp16(sa + row * 128 + ((seg ^ (row & 7)) << 4),
                 Ap + ((bm + row) << 8) + ka + (seg << 3));
        }
#pragma unroll
        for (int i = 0; i < 4; i++) {
            int u = tid + (i << 8);
            int row = u >> 3, seg = u & 7;
            cp16(sb + row * 128 + ((seg ^ (row & 7)) << 4),
                 Bp + (bn + row) * 512 + kb + (seg << 3));
        }
        cp_commit();
    };

    const int a_row = wm * 32 + (lane & 15);
    const int a_kh = lane >> 4;
    const int b_nrel = ((lane >> 4) << 3) + (lane & 7);
    const int b_n = wn * 64 + b_nrel;
    const int b_kh = (lane >> 3) & 1;

    float acc[2][8][4];
#pragma unroll
    for (int mt = 0; mt < 2; mt++)
#pragma unroll
        for (int nt = 0; nt < 8; nt++)
#pragma unroll
            for (int q = 0; q < 4; q++) acc[mt][nt][q] = 0.f;

    issue(0); issue(1); issue(2);

    for (int c = 0; c < NC; c++) {
        cp_wait<STAGES - 1>();
        __syncthreads();
        const unsigned sa = sbase + (c % STAGES) * BUF_SZ;
        const unsigned sb = sa + 16384;
#pragma unroll
        for (int ks = 0; ks < 4; ks++) {
            const int seg0 = ks * 2;
            unsigned af[2][4];
#pragma unroll
            for (int mt = 0; mt < 2; mt++) {
                int r = a_row + mt * 16;
                ldsm_x4(af[mt], sa + r * 128 + (((seg0 + a_kh) ^ (r & 7)) << 4));
            }
            unsigned bf[8][2];
#pragma unroll
            for (int np = 0; np < 4; np++) {
                int n = b_n + np * 16;
                unsigned t4[4];
                ldsm_x4(t4, sb + n * 128 + (((seg0 + b_kh) ^ (n & 7)) << 4));
                bf[np * 2][0] = t4[0]; bf[np * 2][1] = t4[1];
                bf[np * 2 + 1][0] = t4[2]; bf[np * 2 + 1][1] = t4[3];
            }
#pragma unroll
            for (int mt = 0; mt < 2; mt++)
#pragma unroll
                for (int nt = 0; nt < 8; nt++)
                    mma_fp16(acc[mt][nt], af[mt], bf[nt]);
        }
        __syncthreads();
        if (c + STAGES < NC) issue(c + STAGES);
    }
    __syncthreads();

    // ---- epilogue: regs -> staged fp32 tile ----
    const int er = lane >> 2;
    const int ec = (lane & 3) << 1;
#pragma unroll
    for (int mt = 0; mt < 2; mt++) {
#pragma unroll
        for (int nt = 0; nt < 8; nt++) {
            int r0 = wm * 32 + mt * 16 + er;
            int cc = wn * 64 + nt * 8 + ec;
            float b0 = bias[bn + cc], b1 = bias[bn + cc + 1];
            float v0 = acc[mt][nt][0] + b0, v1 = acc[mt][nt][1] + b1;
            float v2 = acc[mt][nt][2] + b0, v3 = acc[mt][nt][3] + b1;
            if (MODE == 1 || MODE == 2) {
                v0 = fmaxf(v0, 0.f); v1 = fmaxf(v1, 0.f);
                v2 = fmaxf(v2, 0.f); v3 = fmaxf(v3, 0.f);
            }
            int r1 = r0 + 8;
            *(float2*)(smem + r0 * 512 + ((((cc >> 2) ^ ((r0 & 7) << 2))) << 4) + ((cc & 3) << 2)) = make_float2(v0, v1);
            *(float2*)(smem + r1 * 512 + ((((cc >> 2) ^ ((r1 & 7) << 2))) << 4) + ((cc & 3) << 2)) = make_float2(v2, v3);
        }
    }
    __syncthreads();

    // ---- staged -> global (plus fused x concat copy when XCOPY) ----
#pragma unroll 4
    for (int i = 0; i < 16; i++) {
        int u = tid + (i << 8);
        int r = u >> 5, seg = u & 31;
        float4 v = *(const float4*)(smem + r * 512 + ((seg ^ ((r & 7) << 2)) << 4));
        int grow = bm + r;
        int gcol = bn + (seg << 2);
        if (F32S) {
            *(float4*)(outf + grow * ldout + gcol) = v;
            if (XCOPY) {
                float4 xv = ((const float4*)xsrc)[(grow << 6) + (gcol >> 2)];
                *(float4*)(outf + grow * ldout + 256 + gcol) = xv;
            }
        }
        if (HST)  ((uint2*)oh)[(grow << 6) + (gcol >> 2)] = pack4h(v);
    }

    // ---- BN stats (MODE 2) ----
    if (MODE == 2) {
        int c = tid & 127, r0 = (tid >> 7) << 6;
        float s = 0.f, q = 0.f;
#pragma unroll 4
        for (int rr = 0; rr < 64; rr++) {
            int r = r0 + rr;
            float v = *(const float*)(smem + r * 512 +
                                      ((((c >> 2) ^ ((r & 7) << 2))) << 4) + ((c & 3) << 2));
            s += v;
            q += v * v;
        }
        float* st = (float*)(smem + STATS_OFF);
        if (tid >= 128) { st[c] = s; st[128 + c] = q; }
        __syncthreads();
        if (tid < 128) {
            atomicAdd(&sumP[bn + c], s + st[c]);
            atomicAdd(&sqP [bn + c], q + st[128 + c]);
        }
    }
}

// ============== aux streams/events (created at static init, pre-checkpoint) ==
struct AuxRes {
    cudaStream_t s1, s2;
    cudaEvent_t fork, e_conv, e_scat, e_w, e_spmm2;
    AuxRes() {
        cudaStreamCreateWithFlags(&s1, cudaStreamNonBlocking);
        cudaStreamCreateWithFlags(&s2, cudaStreamNonBlocking);
        cudaEventCreateWithFlags(&fork,    cudaEventDisableTiming);
        cudaEventCreateWithFlags(&e_conv,  cudaEventDisableTiming);
        cudaEventCreateWithFlags(&e_scat,  cudaEventDisableTiming);
        cudaEventCreateWithFlags(&e_w,     cudaEventDisableTiming);
        cudaEventCreateWithFlags(&e_spmm2, cudaEventDisableTiming);
    }
};
static AuxRes g_aux;   // constructed before main -> before harness checkpoints

// ================= host orchestration ========================================
extern "C" void kernel_launch(void* const* d_in, const int* in_sizes, int n_in,
                              void* d_out, int out_size) {
    (void)in_sizes; (void)n_in; (void)out_size;

    const float* x  = (const float*)d_in[0];
    const int*   ei = (const int*)d_in[2];

    const float* P1[14];
    const float* P2[14];
    for (int i = 0; i < 14; i++) {
        P1[i] = (const float*)d_in[4 + i];
        P2[i] = (const float*)d_in[18 + i];
    }
    // P: 0 ew, 1 eb, 2 nw, 3 nb, 4 c1w, 5 c1b, 6 c2w, 7 c2b,
    //    8 f1w, 9 f1b, 10 bng, 11 bnb, 12 f2w, 13 f2b

    cudaFuncSetAttribute(gemm_mma<1, false, true, false>,
                         cudaFuncAttributeMaxDynamicSharedMemorySize, SMEM_MMA);
    cudaFuncSetAttribute(gemm_mma<2, false, true, false>,
                         cudaFuncAttributeMaxDynamicSharedMemorySize, SMEM_MMA);
    cudaFuncSetAttribute(gemm_mma<3, true, false, true>,
                         cudaFuncAttributeMaxDynamicSharedMemorySize, SMEM_MMA);

    __half *xh, *eh, *eh2, *rh, *qh, *Bw1a, *Bf1a, *Bw1b, *Bf1b, *Bwx, *B2, *Bf2;
    __half *ew1h, *ew2h;
    float *br, *b3, *sum1, *sq1, *sum2, *sq2;
    cudaGetSymbolAddress((void**)&xh,   g_x);
    cudaGetSymbolAddress((void**)&eh,   g_e);
    cudaGetSymbolAddress((void**)&eh2,  g_e2);
    cudaGetSymbolAddress((void**)&rh,   g_r);
    cudaGetSymbolAddress((void**)&qh,   g_q);
    cudaGetSymbolAddress((void**)&ew1h, g_ew1h);
    cudaGetSymbolAddress((void**)&ew2h, g_ew2h);
    cudaGetSymbolAddress((void**)&Bw1a, g_Bw1a);
    cudaGetSymbolAddress((void**)&Bf1a, g_Bf1a);
    cudaGetSymbolAddress((void**)&Bw1b, g_Bw1b);
    cudaGetSymbolAddress((void**)&Bf1b, g_Bf1b);
    cudaGetSymbolAddress((void**)&Bwx,  g_Bwx);
    cudaGetSymbolAddress((void**)&B2,   g_B2);
    cudaGetSymbolAddress((void**)&Bf2,  g_Bf2);
    cudaGetSymbolAddress((void**)&br,   g_biasr);
    cudaGetSymbolAddress((void**)&b3,   g_bias3);
    cudaGetSymbolAddress((void**)&sum1, g_sum1);
    cudaGetSymbolAddress((void**)&sq1,  g_sq1);
    cudaGetSymbolAddress((void**)&sum2, g_sum2);
    cudaGetSymbolAddress((void**)&sq2,  g_sq2);

    float* out = (float*)d_out;
    dim3 grid(2, 128);

    // ---- fork aux branches off the main (capture) stream ----
    cudaEventRecord(g_aux.fork, 0);
    cudaStreamWaitEvent(g_aux.s1, g_aux.fork, 0);
    cudaStreamWaitEvent(g_aux.s2, g_aux.fork, 0);

    // Branch A (s1): conversions + stats zero; later spmm layer2
    conv_k<<<12289, 256, 0, g_aux.s1>>>(x, P1[0], P2[0], xh);
    cudaEventRecord(g_aux.e_conv, g_aux.s1);

    // Branch B (s2): weight-prep chain
    wx2_k<<<dim3(4, 4), 256, 0, g_aux.s2>>>(P2[2], P2[6]);
    wx_pair_k<<<dim3(4, 4, 2), 256, 0, g_aux.s2>>>(P1[2], P1[6], P1[12]);
    splitw_all_k<<<1025, 256, 0, g_aux.s2>>>(P1[4], P1[8], P2[4], P2[8],
                                             P1[3], P1[5], P1[7], P1[6]);
    cudaEventRecord(g_aux.e_w, g_aux.s2);

    // Main stream: CSR chain
    zero_deg_k<<<64, 256>>>();
    hist_k<<<N_EDGES / 256, 256>>>(ei);
    scan_k<<<1, 1024>>>();
    scatter_k<<<N_EDGES / 256, 256>>>(ei);
    cudaEventRecord(g_aux.e_scat, 0);

    // Branch A continues: spmm layer2 (needs conv [program order] + scatter)
    cudaStreamWaitEvent(g_aux.s1, g_aux.e_scat, 0);
    spmm_k<<<4096, 256, 0, g_aux.s1>>>(ew2h, P2[1], eh2);
    cudaEventRecord(g_aux.e_spmm2, g_aux.s1);

    // Main: spmm layer1 (needs conv)
    cudaStreamWaitEvent(0, g_aux.e_conv, 0);
    spmm_k<<<4096, 256>>>(ew1h, P1[1], eh);

    // Main: GEMM chain (join weights)
    cudaStreamWaitEvent(0, g_aux.e_w, 0);
    // r1 = relu(emb1@(I+c1w1) + x@wx1 + biasr1)
    gemm_mma<1, false, true, false><<<grid, 256, SMEM_MMA>>>(
        eh, xh, Bw1a, Bwx, br, nullptr, 0, rh, nullptr, nullptr, nullptr);
    // q1 = relu(r1@f1w1 + f1b1), stats1
    gemm_mma<2, false, true, false><<<grid, 256, SMEM_MMA>>>(
        rh, nullptr, Bf1a, nullptr, P1[9], nullptr, 0, qh, sum1, sq1, nullptr);
    // B2 = diag(s1)@G ; biasr = layer2 fused bias (+ layer1 tail)
    bneff2_k<<<257, 256>>>(P1[10], P1[11], P1[13], P2[3], P2[5], P2[7], P2[6]);
    // join spmm layer2
    cudaStreamWaitEvent(0, g_aux.e_spmm2, 0);
    // r2 = relu(emb2@(I+c1w2) + q1@B2 + biasr)
    gemm_mma<1, false, true, false><<<grid, 256, SMEM_MMA>>>(
        eh2, qh, Bw1b, B2, br, nullptr, 0, rh, nullptr, nullptr, nullptr);
    // q2 = relu(r2@f1w2 + f1b2), stats2
    gemm_mma<2, false, true, false><<<grid, 256, SMEM_MMA>>>(
        rh, nullptr, Bf1b, nullptr, P2[9], nullptr, 0, qh, sum2, sq2, nullptr);
    // fold BN2 into f2w2 + bias3
    bnfold_k<<<257, 256>>>(P2[10], P2[11], P2[12], P2[13]);
    // out[:,0:256] = (q2*s2+t2)@f2w2 + f2b2 ; out[:,256:512] = x (fused)
    gemm_mma<3, true, false, true><<<grid, 256, SMEM_MMA>>>(
        qh, nullptr, Bf2, nullptr, b3, out, 512, nullptr, nullptr, nullptr, x);
}

// round 12
// speedup vs baseline: 1.0681x; 1.0681x over previous
#include <cuda_runtime.h>
#include <cuda_fp16.h>

#define N_NODES 16384
#define N_EDGES 262144
#define D_CH    256
#define BN_EPS  1e-5f

// ================= device scratch (no runtime allocation) ==================
__device__ __half g_x [N_NODES * D_CH];
__device__ __half g_e [N_NODES * D_CH];
__device__ __half g_e2[N_NODES * D_CH];
__device__ __half g_r [N_NODES * D_CH];
__device__ __half g_q [N_NODES * D_CH];

// fp16 copies of the edge-weight tables
__device__ __half g_ew1h[N_NODES * D_CH];
__device__ __half g_ew2h[N_NODES * D_CH];

// stacked split weights, layout [N=256 rows][K'=512]: [hi(256) | lo(256)]
__device__ __half g_Bw1a[D_CH * 512];
__device__ __half g_Bf1a[D_CH * 512];
__device__ __half g_Bw1b[D_CH * 512];
__device__ __half g_Bf1b[D_CH * 512];
__device__ __half g_Bwx [D_CH * 512];
__device__ __half g_B2  [D_CH * 512];
__device__ __half g_Bf2 [D_CH * 512];

__device__ float g_wx1[D_CH * D_CH];   // nw1 @ (I + c2w1), fp32
__device__ float g_wx2[D_CH * D_CH];   // nw2 @ (I + c2w2), fp32
__device__ float g_G  [D_CH * D_CH];   // f2w1 @ wx2, fp32

__device__ float g_biasr[D_CH];
__device__ float g_bias3[D_CH];

__device__ float g_sum1[D_CH];
__device__ float g_sq1 [D_CH];
__device__ float g_sum2[D_CH];
__device__ float g_sq2 [D_CH];

__device__ int g_deg[N_NODES];
__device__ int g_off[N_NODES + 1];
__device__ int g_cur[N_NODES];
__device__ int g_csr[N_EDGES];

// ================= PTX helpers (sm_100 BASE ISA only) =======================
__device__ __forceinline__ unsigned smem_u32(const void* p) {
    unsigned a;
    asm("{ .reg .u64 t; cvta.to.shared.u64 t, %1; cvt.u32.u64 %0, t; }"
        : "=r"(a) : "l"(p));
    return a;
}

__device__ __forceinline__ void cp16(unsigned dst, const void* src) {
    asm volatile("cp.async.cg.shared.global [%0], [%1], 16;"
                 :: "r"(dst), "l"(src) : "memory");
}
__device__ __forceinline__ void cp_commit() {
    asm volatile("cp.async.commit_group;" ::: "memory");
}
template <int N>
__device__ __forceinline__ void cp_wait() {
    asm volatile("cp.async.wait_group %0;" :: "n"(N) : "memory");
}

__device__ __forceinline__ void ldsm_x4(unsigned* r, unsigned addr) {
    asm volatile("ldmatrix.sync.aligned.m8n8.x4.shared.b16 {%0,%1,%2,%3}, [%4];"
                 : "=r"(r[0]), "=r"(r[1]), "=r"(r[2]), "=r"(r[3]) : "r"(addr));
}

__device__ __forceinline__ void mma_fp16(float* c, const unsigned* a, const unsigned* b) {
    asm volatile(
        "mma.sync.aligned.m16n8k16.row.col.f32.f16.f16.f32 "
        "{%0,%1,%2,%3}, {%4,%5,%6,%7}, {%8,%9}, {%0,%1,%2,%3};"
        : "+f"(c[0]), "+f"(c[1]), "+f"(c[2]), "+f"(c[3])
        : "r"(a[0]), "r"(a[1]), "r"(a[2]), "r"(a[3]), "r"(b[0]), "r"(b[1]));
}

__device__ __forceinline__ void split1h(float v, __half& h, __half& l) {
    h = __float2half_rn(v);
    l = __float2half_rn(v - __half2float(h));
}
__device__ __forceinline__ uint2 pack4h(float4 v) {
    __half2 a = __floats2half2_rn(v.x, v.y);
    __half2 b = __floats2half2_rn(v.z, v.w);
    uint2 r;
    r.x = *(unsigned*)&a;
    r.y = *(unsigned*)&b;
    return r;
}

// ===== fused prep: split x + fp16 ew tables + zero deg/stats ================
__global__ void prep_k(const float* __restrict__ x,
                       const float* __restrict__ ew1,
                       const float* __restrict__ ew2,
                       __half* __restrict__ xh) {
    int b = blockIdx.x;
    if (b < 4096) {
        int i = b * 256 + threadIdx.x;
        ((uint2*)xh)[i] = pack4h(((const float4*)x)[i]);
    } else if (b < 8192) {
        int i = (b - 4096) * 256 + threadIdx.x;
        ((uint2*)g_ew1h)[i] = pack4h(((const float4*)ew1)[i]);
    } else if (b < 12288) {
        int i = (b - 8192) * 256 + threadIdx.x;
        ((uint2*)g_ew2h)[i] = pack4h(((const float4*)ew2)[i]);
    } else if (b < 12352) {
        g_deg[(b - 12288) * 256 + threadIdx.x] = 0;
    } else {
        int j = threadIdx.x;
        g_sum1[j] = 0.f; g_sq1[j] = 0.f;
        g_sum2[j] = 0.f; g_sq2[j] = 0.f;
    }
}

// ================= CSR construction =========================================
__global__ void hist_k(const int* __restrict__ ei) {
    int e = blockIdx.x * 256 + threadIdx.x;
    if (e < N_EDGES) atomicAdd(&g_deg[ei[N_EDGES + e]], 1);
}
__global__ void scan_k() {   // also initializes g_cur
    __shared__ int s[1024];
    int t = threadIdx.x;
    int base = t * 16;
    int local[16];
    int sum = 0;
#pragma unroll
    for (int i = 0; i < 16; i++) { local[i] = g_deg[base + i]; sum += local[i]; }
    s[t] = sum;
    __syncthreads();
    for (int d = 1; d < 1024; d <<= 1) {
        int v = 0;
        if (t >= d) v = s[t - d];
        __syncthreads();
        if (t >= d) s[t] += v;
        __syncthreads();
    }
    int prefix = (t == 0) ? 0 : s[t - 1];
    int run = prefix;
#pragma unroll
    for (int i = 0; i < 16; i++) {
        g_off[base + i] = run;
        g_cur[base + i] = run;
        run += local[i];
    }
    if (t == 1023) g_off[N_NODES] = run;
}
__global__ void scatter_k(const int* __restrict__ ei) {
    int e = blockIdx.x * 256 + threadIdx.x;
    if (e < N_EDGES) {
        int d = ei[N_EDGES + e];
        int p = atomicAdd(&g_cur[d], 1);
        g_csr[p] = ei[e];
    }
}

// ================= SpMM both layers (fp16 gather) -> fp16 ===================
__global__ void spmm_both_k(const float* __restrict__ eb1,
                            const float* __restrict__ eb2,
                            __half* __restrict__ e1, __half* __restrict__ e2) {
    int b = blockIdx.x;                 // 0..8191
    int layer = b >> 12;
    const __half* ew = layer ? g_ew2h : g_ew1h;
    const float* eb = layer ? eb2 : eb1;
    __half* eo = layer ? e2 : e1;
    int node = (b & 4095) * 4 + (threadIdx.x >> 6);
    int c = threadIdx.x & 63;
    const uint2* ew4 = (const uint2*)ew;
    float4 acc = ((const float4*)eb)[c];
    int s = g_off[node];
    int e = g_off[node + 1];
    for (int k = s; k < e; k++) {
        int j = g_csr[k];
        uint2 v = ew4[j * 64 + c];
        float2 f0 = __half22float2(*(const __half2*)&v.x);
        float2 f1 = __half22float2(*(const __half2*)&v.y);
        acc.x += f0.x; acc.y += f0.y; acc.z += f1.x; acc.w += f1.y;
    }
    ((uint2*)eo)[node * 64 + c] = pack4h(acc);
}

// ========== small fp32 GEMM tile (64x64, reg double-buffer, fp32 out) =======
template <bool ADD_A>
__device__ __forceinline__ void wx_tile(const float* __restrict__ A,
                                        const float* __restrict__ B,
                                        float* __restrict__ Cf,
                                        int bm, int bn) {
    __shared__ float As[16][64];
    __shared__ float Bs[16][68];
    int tx = threadIdx.x & 15, ty = threadIdx.x >> 4;
    int r = threadIdx.x >> 2, c4 = (threadIdx.x & 3) * 4;
    int rb = threadIdx.x >> 4, cb = (threadIdx.x & 15) * 4;
    float acc[4][4] = {};
    float4 av = *(const float4*)(A + (bm + r) * 256 + c4);
    float4 bv = *(const float4*)(B + rb * 256 + bn + cb);
    for (int kt = 0; kt < 256; kt += 16) {
        As[c4 + 0][r] = av.x; As[c4 + 1][r] = av.y;
        As[c4 + 2][r] = av.z; As[c4 + 3][r] = av.w;
        *(float4*)&Bs[rb][cb] = bv;
        __syncthreads();
        if (kt < 240) {
            av = *(const float4*)(A + (bm + r) * 256 + kt + 16 + c4);
            bv = *(const float4*)(B + (kt + 16 + rb) * 256 + bn + cb);
        }
#pragma unroll
        for (int k = 0; k < 16; k++) {
            float a[4], b[4];
#pragma unroll
            for (int i = 0; i < 4; i++) a[i] = As[k][ty * 4 + i];
#pragma unroll
            for (int j = 0; j < 4; j++) b[j] = Bs[k][tx * 4 + j];
#pragma unroll
            for (int i = 0; i < 4; i++)
#pragma unroll
                for (int j = 0; j < 4; j++) acc[i][j] = fmaf(a[i], b[j], acc[i][j]);
        }
        __syncthreads();
    }
#pragma unroll
    for (int i = 0; i < 4; i++) {
        int k = bm + ty * 4 + i;
#pragma unroll
        for (int j = 0; j < 4; j++) {
            int n = bn + tx * 4 + j;
            float w = acc[i][j];
            if (ADD_A) w += A[k * 256 + n];
            Cf[k * 256 + n] = w;   // coalesced fp32 store
        }
    }
}

// wx2 = nw2 @ c2w2 + nw2
__global__ void wx2_k(const float* __restrict__ nw2, const float* __restrict__ c2w2) {
    wx_tile<true>(nw2, c2w2, g_wx2, blockIdx.y * 64, blockIdx.x * 64);
}
// z=0: wx1 = nw1 @ c2w1 + nw1;  z=1: G = f2w1 @ wx2
__global__ void wx_pair_k(const float* __restrict__ nw1, const float* __restrict__ c2w1,
                          const float* __restrict__ f2w1) {
    if (blockIdx.z == 0)
        wx_tile<true>(nw1, c2w1, g_wx1, blockIdx.y * 64, blockIdx.x * 64);
    else
        wx_tile<false>(f2w1, g_wx2, g_G, blockIdx.y * 64, blockIdx.x * 64);
}

// ===== coalesced transpose-split: 5 matrices (64x64 smem tiles) + biasr1 ====
// W is [k][n] row-major; B output [n][512] gets hi at col k, lo at col 256+k.
__global__ void splitw_all_k(const float* __restrict__ c1w1, const float* __restrict__ f1w1,
                             const float* __restrict__ c1w2, const float* __restrict__ f1w2,
                             const float* __restrict__ nb1, const float* __restrict__ c1b1,
                             const float* __restrict__ c2b1, const float* __restrict__ c2w1) {
    __shared__ float T[64][65];
    int b = blockIdx.x;
    if (b < 80) {
        int mat = b >> 4;
        int t = b & 15;
        int kt = (t & 3) * 64, nt = (t >> 2) * 64;
        const float* W;
        __half* B;
        bool addI = false;
        switch (mat) {
            case 0: W = c1w1; B = g_Bw1a; addI = true; break;
            case 1: W = f1w1; B = g_Bf1a; break;
            case 2: W = c1w2; B = g_Bw1b; addI = true; break;
            case 3: W = f1w2; B = g_Bf1b; break;
            default: W = g_wx1; B = g_Bwx; break;
        }
        int r4 = threadIdx.x >> 6;      // 0..3
        int c = threadIdx.x & 63;       // 0..63
#pragma unroll
        for (int i = 0; i < 16; i++) {
            int row = i * 4 + r4;       // k within tile
            float w = W[(kt + row) * 256 + nt + c];
            if (addI && (kt + row) == (nt + c)) w += 1.f;
            T[row][c] = w;
        }
        __syncthreads();
#pragma unroll
        for (int i = 0; i < 16; i++) {
            int nl = i * 4 + r4;        // n within tile
            __half h, l;
            split1h(T[c][nl], h, l);    // c = k within tile
            B[(nt + nl) * 512 + kt + c]       = h;
            B[(nt + nl) * 512 + 256 + kt + c] = l;
        }
    } else {
        int n = threadIdx.x;
        float s = c1b1[n] + c2b1[n] + nb1[n];
        for (int k = 0; k < 256; k++) s += nb1[k] * c2w1[k * 256 + n];
        g_biasr[n] = s;
    }
}

// ===== bneff2: B2 = diag(s1)@G transpose-split (16 tiles) + layer2 bias =====
__global__ void bneff2_k(const float* __restrict__ g1, const float* __restrict__ b1,
                         const float* __restrict__ f2b1,
                         const float* __restrict__ nb2, const float* __restrict__ c1b2,
                         const float* __restrict__ c2b2, const float* __restrict__ c2w2) {
    const float inv_n = 1.f / (float)N_NODES;
    int b = blockIdx.x;
    if (b < 16) {
        __shared__ float T[64][65];
        __shared__ float sc[64];
        int kt = (b & 3) * 64, nt = (b >> 2) * 64;
        if (threadIdx.x < 64) {
            int k = kt + threadIdx.x;
            float mu = g_sum1[k] * inv_n;
            float var = g_sq1[k] * inv_n - mu * mu;
            sc[threadIdx.x] = rsqrtf(var + BN_EPS) * g1[k];
        }
        __syncthreads();
        int r4 = threadIdx.x >> 6;
        int c = threadIdx.x & 63;
#pragma unroll
        for (int i = 0; i < 16; i++) {
            int row = i * 4 + r4;
            T[row][c] = sc[row] * g_G[(kt + row) * 256 + nt + c];
        }
        __syncthreads();
#pragma unroll
        for (int i = 0; i < 16; i++) {
            int nl = i * 4 + r4;
            __half h, l;
            split1h(T[c][nl], h, l);
            g_B2[(nt + nl) * 512 + kt + c]       = h;
            g_B2[(nt + nl) * 512 + 256 + kt + c] = l;
        }
    } else {
        int n = threadIdx.x;
        float s = c1b2[n] + c2b2[n] + nb2[n];
        for (int k = 0; k < 256; k++) {
            float mu = g_sum1[k] * inv_n;
            float var = g_sq1[k] * inv_n - mu * mu;
            float rs = rsqrtf(var + BN_EPS);
            float t1 = b1[k] - mu * rs * g1[k];
            s += nb2[k] * c2w2[k * 256 + n] + t1 * g_G[(k << 8) + n]
               + f2b1[k] * g_wx2[(k << 8) + n];
        }
        g_biasr[n] = s;
    }
}

// ===== bnfold: Bf2 = diag(s2)@f2w2 transpose-split (16 tiles) + bias3 =======
__global__ void bnfold_k(const float* __restrict__ gamma, const float* __restrict__ beta,
                         const float* __restrict__ f2w, const float* __restrict__ f2b) {
    const float inv_n = 1.f / (float)N_NODES;
    int b = blockIdx.x;
    if (b < 16) {
        __shared__ float T[64][65];
        __shared__ float sc[64];
        int kt = (b & 3) * 64, nt = (b >> 2) * 64;
        if (threadIdx.x < 64) {
            int k = kt + threadIdx.x;
            float mu = g_sum2[k] * inv_n;
            float var = g_sq2[k] * inv_n - mu * mu;
            sc[threadIdx.x] = rsqrtf(var + BN_EPS) * gamma[k];
        }
        __syncthreads();
        int r4 = threadIdx.x >> 6;
        int c = threadIdx.x & 63;
#pragma unroll
        for (int i = 0; i < 16; i++) {
            int row = i * 4 + r4;
            T[row][c] = sc[row] * f2w[(kt + row) * 256 + nt + c];
        }
        __syncthreads();
#pragma unroll
        for (int i = 0; i < 16; i++) {
            int nl = i * 4 + r4;
            __half h, l;
            split1h(T[c][nl], h, l);
            g_Bf2[(nt + nl) * 512 + kt + c]       = h;
            g_Bf2[(nt + nl) * 512 + 256 + kt + c] = l;
        }
    } else {
        int n = threadIdx.x;
        float s = f2b[n];
        for (int k = 0; k < 256; k++) {
            float mu = g_sum2[k] * inv_n;
            float var = g_sq2[k] * inv_n - mu * mu;
            float rs = rsqrtf(var + BN_EPS);
            s += (beta[k] - mu * rs * gamma[k]) * f2w[(k << 8) + n];
        }
        g_bias3[n] = s;
    }
}

// ================= HMMA fp16 2-term GEMM =====================================
#define STAGES   3
#define BUF_SZ   32768
#define STATS_OFF (STAGES * BUF_SZ)
#define SMEM_MMA (STATS_OFF + 1024)

template <int MODE, bool F32S, bool HST, bool XCOPY>
__global__ void __launch_bounds__(256, 2)
gemm_mma(const __half* __restrict__ A, const __half* __restrict__ A2,
         const __half* __restrict__ Bb, const __half* __restrict__ B2b,
         const float* __restrict__ bias,
         float* __restrict__ outf, int ldout,
         __half* __restrict__ oh,
         float* __restrict__ sumP, float* __restrict__ sqP,
         const float* __restrict__ xsrc) {
    extern __shared__ char smem[];
    const unsigned sbase = smem_u32(smem);
    const int tid = threadIdx.x;
    const int lane = tid & 31;
    const int w = tid >> 5;
    const int wm = w & 3;
    const int wn = w >> 2;
    const int bm = blockIdx.y * 128;
    const int bn = blockIdx.x * 128;

    const int NC = (MODE == 1) ? 16 : 8;

    auto issue = [&](int c) {
        const bool second = (MODE == 1) && (c >= 8);
        const int local = second ? c - 8 : c;
        const __half* Ap = second ? A2 : A;
        const __half* Bp = second ? B2b : Bb;
        const int ka = (local & 3) << 6;
        const int kb = local << 6;
        const unsigned sa = sbase + (c % STAGES) * BUF_SZ;
        const unsigned sb = sa + 16384;
#pragma unroll
        for (int i = 0; i < 4; i++) {
            int u = tid + (i << 8);
            int row = u >> 3, seg = u & 7;
            cp16(sa + row * 128 + ((seg ^ (row & 7)) << 4),
                 Ap + ((bm + row) << 8) + ka + (seg << 3));
        }
#pragma unroll
        for (int i = 0; i < 4; i++) {
            int u = tid + (i << 8);
            int row = u >> 3, seg = u & 7;
            cp16(sb + row * 128 + ((seg ^ (row & 7)) << 4),
                 Bp + (bn + row) * 512 + kb + (seg << 3));
        }
        cp_commit();
    };

    const int a_row = wm * 32 + (lane & 15);
    const int a_kh = lane >> 4;
    const int b_nrel = ((lane >> 4) << 3) + (lane & 7);
    const int b_n = wn * 64 + b_nrel;
    const int b_kh = (lane >> 3) & 1;

    float acc[2][8][4];
#pragma unroll
    for (int mt = 0; mt < 2; mt++)
#pragma unroll
        for (int nt = 0; nt < 8; nt++)
#pragma unroll
            for (int q = 0; q < 4; q++) acc[mt][nt][q] = 0.f;

    issue(0); issue(1); issue(2);

    for (int c = 0; c < NC; c++) {
        cp_wait<STAGES - 1>();
        __syncthreads();
        const unsigned sa = sbase + (c % STAGES) * BUF_SZ;
        const unsigned sb = sa + 16384;
#pragma unroll
        for (int ks = 0; ks < 4; ks++) {
            const int seg0 = ks * 2;
            unsigned af[2][4];
#pragma unroll
            for (int mt = 0; mt < 2; mt++) {
                int r = a_row + mt * 16;
                ldsm_x4(af[mt], sa + r * 128 + (((seg0 + a_kh) ^ (r & 7)) << 4));
            }
            unsigned bf[8][2];
#pragma unroll
            for (int np = 0; np < 4; np++) {
                int n = b_n + np * 16;
                unsigned t4[4];
                ldsm_x4(t4, sb + n * 128 + (((seg0 + b_kh) ^ (n & 7)) << 4));
                bf[np * 2][0] = t4[0]; bf[np * 2][1] = t4[1];
                bf[np * 2 + 1][0] = t4[2]; bf[np * 2 + 1][1] = t4[3];
            }
#pragma unroll
            for (int mt = 0; mt < 2; mt++)
#pragma unroll
                for (int nt = 0; nt < 8; nt++)
                    mma_fp16(acc[mt][nt], af[mt], bf[nt]);
        }
        __syncthreads();
        if (c + STAGES < NC) issue(c + STAGES);
    }
    __syncthreads();

    // ---- epilogue: regs -> staged fp32 tile ----
    const int er = lane >> 2;
    const int ec = (lane & 3) << 1;
#pragma unroll
    for (int mt = 0; mt < 2; mt++) {
#pragma unroll
        for (int nt = 0; nt < 8; nt++) {
            int r0 = wm * 32 + mt * 16 + er;
            int cc = wn * 64 + nt * 8 + ec;
            float b0 = bias[bn + cc], b1 = bias[bn + cc + 1];
            float v0 = acc[mt][nt][0] + b0, v1 = acc[mt][nt][1] + b1;
            float v2 = acc[mt][nt][2] + b0, v3 = acc[mt][nt][3] + b1;
            if (MODE == 1 || MODE == 2) {
                v0 = fmaxf(v0, 0.f); v1 = fmaxf(v1, 0.f);
                v2 = fmaxf(v2, 0.f); v3 = fmaxf(v3, 0.f);
            }
            int r1 = r0 + 8;
            *(float2*)(smem + r0 * 512 + ((((cc >> 2) ^ ((r0 & 7) << 2))) << 4) + ((cc & 3) << 2)) = make_float2(v0, v1);
            *(float2*)(smem + r1 * 512 + ((((cc >> 2) ^ ((r1 & 7) << 2))) << 4) + ((cc & 3) << 2)) = make_float2(v2, v3);
        }
    }
    __syncthreads();

    // ---- staged -> global (plus fused x concat copy when XCOPY) ----
#pragma unroll 4
    for (int i = 0; i < 16; i++) {
        int u = tid + (i << 8);
        int r = u >> 5, seg = u & 31;
        float4 v = *(const float4*)(smem + r * 512 + ((seg ^ ((r & 7) << 2)) << 4));
        int grow = bm + r;
        int gcol = bn + (seg << 2);
        if (F32S) {
            *(float4*)(outf + grow * ldout + gcol) = v;
            if (XCOPY) {
                float4 xv = ((const float4*)xsrc)[(grow << 6) + (gcol >> 2)];
                *(float4*)(outf + grow * ldout + 256 + gcol) = xv;
            }
        }
        if (HST)  ((uint2*)oh)[(grow << 6) + (gcol >> 2)] = pack4h(v);
    }

    // ---- BN stats (MODE 2) ----
    if (MODE == 2) {
        int c = tid & 127, r0 = (tid >> 7) << 6;
        float s = 0.f, q = 0.f;
#pragma unroll 4
        for (int rr = 0; rr < 64; rr++) {
            int r = r0 + rr;
            float v = *(const float*)(smem + r * 512 +
                                      ((((c >> 2) ^ ((r & 7) << 2))) << 4) + ((c & 3) << 2));
            s += v;
            q += v * v;
        }
        float* st = (float*)(smem + STATS_OFF);
        if (tid >= 128) { st[c] = s; st[128 + c] = q; }
        __syncthreads();
        if (tid < 128) {
            atomicAdd(&sumP[bn + c], s + st[c]);
            atomicAdd(&sqP [bn + c], q + st[128 + c]);
        }
    }
}

// ================= host orchestration ========================================
extern "C" void kernel_launch(void* const* d_in, const int* in_sizes, int n_in,
                              void* d_out, int out_size) {
    (void)in_sizes; (void)n_in; (void)out_size;

    const float* x  = (const float*)d_in[0];
    const int*   ei = (const int*)d_in[2];

    const float* P1[14];
    const float* P2[14];
    for (int i = 0; i < 14; i++) {
        P1[i] = (const float*)d_in[4 + i];
        P2[i] = (const float*)d_in[18 + i];
    }
    // P: 0 ew, 1 eb, 2 nw, 3 nb, 4 c1w, 5 c1b, 6 c2w, 7 c2b,
    //    8 f1w, 9 f1b, 10 bng, 11 bnb, 12 f2w, 13 f2b

    cudaFuncSetAttribute(gemm_mma<1, false, true, false>,
                         cudaFuncAttributeMaxDynamicSharedMemorySize, SMEM_MMA);
    cudaFuncSetAttribute(gemm_mma<2, false, true, false>,
                         cudaFuncAttributeMaxDynamicSharedMemorySize, SMEM_MMA);
    cudaFuncSetAttribute(gemm_mma<3, true, false, true>,
                         cudaFuncAttributeMaxDynamicSharedMemorySize, SMEM_MMA);

    __half *xh, *eh, *eh2, *rh, *qh, *Bw1a, *Bf1a, *Bw1b, *Bf1b, *Bwx, *B2, *Bf2;
    float *br, *b3, *sum1, *sq1, *sum2, *sq2;
    cudaGetSymbolAddress((void**)&xh,   g_x);
    cudaGetSymbolAddress((void**)&eh,   g_e);
    cudaGetSymbolAddress((void**)&eh2,  g_e2);
    cudaGetSymbolAddress((void**)&rh,   g_r);
    cudaGetSymbolAddress((void**)&qh,   g_q);
    cudaGetSymbolAddress((void**)&Bw1a, g_Bw1a);
    cudaGetSymbolAddress((void**)&Bf1a, g_Bf1a);
    cudaGetSymbolAddress((void**)&Bw1b, g_Bw1b);
    cudaGetSymbolAddress((void**)&Bf1b, g_Bf1b);
    cudaGetSymbolAddress((void**)&Bwx,  g_Bwx);
    cudaGetSymbolAddress((void**)&B2,   g_B2);
    cudaGetSymbolAddress((void**)&Bf2,  g_Bf2);
    cudaGetSymbolAddress((void**)&br,   g_biasr);
    cudaGetSymbolAddress((void**)&b3,   g_bias3);
    cudaGetSymbolAddress((void**)&sum1, g_sum1);
    cudaGetSymbolAddress((void**)&sq1,  g_sq1);
    cudaGetSymbolAddress((void**)&sum2, g_sum2);
    cudaGetSymbolAddress((void**)&sq2,  g_sq2);

    float* out = (float*)d_out;
    dim3 grid(2, 128);

    // 1. fused prep (split x, fp16 ew tables, zero deg, zero stats)
    prep_k<<<12353, 256>>>(x, P1[0], P2[0], xh);
    // 2-4. CSR
    hist_k<<<N_EDGES / 256, 256>>>(ei);
    scan_k<<<1, 1024>>>();
    scatter_k<<<N_EDGES / 256, 256>>>(ei);
    // 5. both layers' SpMM (fp16 gather)
    spmm_both_k<<<8192, 256>>>(P1[1], P2[1], eh, eh2);
    // 6-7. small fp32 weight GEMMs (fp32 coalesced outputs)
    wx2_k<<<dim3(4, 4), 256>>>(P2[2], P2[6]);
    wx_pair_k<<<dim3(4, 4, 2), 256>>>(P1[2], P1[6], P1[12]);
    // 8. coalesced transpose-splits (5 matrices) + layer1 fused bias
    splitw_all_k<<<81, 256>>>(P1[4], P1[8], P2[4], P2[8],
                              P1[3], P1[5], P1[7], P1[6]);

    // 9. r1 = relu(emb1@(I+c1w1) + x@wx1 + biasr1)
    gemm_mma<1, false, true, false><<<grid, 256, SMEM_MMA>>>(
        eh, xh, Bw1a, Bwx, br, nullptr, 0, rh, nullptr, nullptr, nullptr);
    // 10. q1 = relu(r1@f1w1 + f1b1), stats1
    gemm_mma<2, false, true, false><<<grid, 256, SMEM_MMA>>>(
        rh, nullptr, Bf1a, nullptr, P1[9], nullptr, 0, qh, sum1, sq1, nullptr);
    // 11. B2 = diag(s1)@G (transpose-split) ; biasr = layer2 fused bias
    bneff2_k<<<17, 256>>>(P1[10], P1[11], P1[13], P2[3], P2[5], P2[7], P2[6]);
    // 12. r2 = relu(emb2@(I+c1w2) + q1@B2 + biasr)
    gemm_mma<1, false, true, false><<<grid, 256, SMEM_MMA>>>(
        eh2, qh, Bw1b, B2, br, nullptr, 0, rh, nullptr, nullptr, nullptr);
    // 13. q2 = relu(r2@f1w2 + f1b2), stats2
    gemm_mma<2, false, true, false><<<grid, 256, SMEM_MMA>>>(
        rh, nullptr, Bf1b, nullptr, P2[9], nullptr, 0, qh, sum2, sq2, nullptr);
    // 14. fold BN2 into f2w2 (transpose-split) + bias3
    bnfold_k<<<17, 256>>>(P2[10], P2[11], P2[12], P2[13]);
    // 15. out[:,0:256] = (q2*s2+t2)@f2w2 + f2b2 ; out[:,256:512] = x (fused)
    gemm_mma<3, true, false, true><<<grid, 256, SMEM_MMA>>>(
        qh, nullptr, Bf2, nullptr, b3, out, 512, nullptr, nullptr, nullptr, x);
}

// round 13
// speedup vs baseline: 1.1408x; 1.0680x over previous
#include <cuda_runtime.h>
#include <cuda_fp16.h>

#define N_NODES 16384
#define N_EDGES 262144
#define D_CH    256
#define BN_EPS  1e-5f

// ================= device scratch (no runtime allocation) ==================
__device__ __half g_x [N_NODES * D_CH];
__device__ __half g_e [N_NODES * D_CH];
__device__ __half g_e2[N_NODES * D_CH];
__device__ __half g_r [N_NODES * D_CH];
__device__ __half g_q [N_NODES * D_CH];

__device__ __half g_ew1h[N_NODES * D_CH];
__device__ __half g_ew2h[N_NODES * D_CH];

// stacked split weights, [N=256 rows][K'=512]: [hi(256) | lo(256)]
__device__ __half g_Bw1a[D_CH * 512];
__device__ __half g_Bf1a[D_CH * 512];
__device__ __half g_Bw1b[D_CH * 512];
__device__ __half g_Bf1b[D_CH * 512];
__device__ __half g_Bwx [D_CH * 512];
__device__ __half g_B2  [D_CH * 512];
__device__ __half g_Bf2 [D_CH * 512];

__device__ float g_wx1[D_CH * D_CH];
__device__ float g_wx2[D_CH * D_CH];
__device__ float g_G  [D_CH * D_CH];

__device__ float g_biasr[D_CH];
__device__ float g_bias3[D_CH];

__device__ float g_sum1[D_CH];
__device__ float g_sq1 [D_CH];
__device__ float g_sum2[D_CH];
__device__ float g_sq2 [D_CH];

__device__ int g_deg[N_NODES];
__device__ int g_off[N_NODES + 1];
__device__ int g_cur[N_NODES];
__device__ int g_csr[N_EDGES];

__device__ unsigned g_flags[256];   // grid barrier flags (monotone gens)

// ================= PTX helpers ==============================================
__device__ __forceinline__ unsigned smem_u32(const void* p) {
    unsigned a;
    asm("{ .reg .u64 t; cvta.to.shared.u64 t, %1; cvt.u32.u64 %0, t; }"
        : "=r"(a) : "l"(p));
    return a;
}
__device__ __forceinline__ void cp16(unsigned dst, const void* src) {
    asm volatile("cp.async.cg.shared.global [%0], [%1], 16;"
                 :: "r"(dst), "l"(src) : "memory");
}
__device__ __forceinline__ void cp_commit() {
    asm volatile("cp.async.commit_group;" ::: "memory");
}
template <int N>
__device__ __forceinline__ void cp_wait() {
    asm volatile("cp.async.wait_group %0;" :: "n"(N) : "memory");
}
__device__ __forceinline__ void ldsm_x4(unsigned* r, unsigned addr) {
    asm volatile("ldmatrix.sync.aligned.m8n8.x4.shared.b16 {%0,%1,%2,%3}, [%4];"
                 : "=r"(r[0]), "=r"(r[1]), "=r"(r[2]), "=r"(r[3]) : "r"(addr));
}
__device__ __forceinline__ void mma_fp16(float* c, const unsigned* a, const unsigned* b) {
    asm volatile(
        "mma.sync.aligned.m16n8k16.row.col.f32.f16.f16.f32 "
        "{%0,%1,%2,%3}, {%4,%5,%6,%7}, {%8,%9}, {%0,%1,%2,%3};"
        : "+f"(c[0]), "+f"(c[1]), "+f"(c[2]), "+f"(c[3])
        : "r"(a[0]), "r"(a[1]), "r"(a[2]), "r"(a[3]), "r"(b[0]), "r"(b[1]));
}
__device__ __forceinline__ void split1h(float v, __half& h, __half& l) {
    h = __float2half_rn(v);
    l = __float2half_rn(v - __half2float(h));
}
__device__ __forceinline__ uint2 pack4h(float4 v) {
    __half2 a = __floats2half2_rn(v.x, v.y);
    __half2 b = __floats2half2_rn(v.z, v.w);
    uint2 r;
    r.x = *(unsigned*)&a;
    r.y = *(unsigned*)&b;
    return r;
}

// ================= grid barrier (flag array, monotone generations) ==========
__device__ __forceinline__ void grid_bar(unsigned gen) {
    __syncthreads();
    __threadfence();
    if (threadIdx.x == 0) atomicExch(&g_flags[blockIdx.x], gen);
    for (;;) {
        unsigned v = __ldcg(&g_flags[threadIdx.x]);
        if (__syncthreads_and((int)(v - gen) >= 0)) break;
        __nanosleep(128);
    }
    __threadfence();
}

// ================= phase pieces ==============================================
// conv unit (from prep_k): u in [0,12353)
__device__ void conv_unit(unsigned u, const float* x, const float* ew1,
                          const float* ew2) {
    if (u < 4096) {
        int i = u * 256 + threadIdx.x;
        ((uint2*)g_x)[i] = pack4h(((const float4*)x)[i]);
    } else if (u < 8192) {
        int i = (u - 4096) * 256 + threadIdx.x;
        ((uint2*)g_ew1h)[i] = pack4h(((const float4*)ew1)[i]);
    } else if (u < 12288) {
        int i = (u - 8192) * 256 + threadIdx.x;
        ((uint2*)g_ew2h)[i] = pack4h(((const float4*)ew2)[i]);
    } else if (u < 12352) {
        g_deg[(u - 12288) * 256 + threadIdx.x] = 0;
    } else {
        int j = threadIdx.x;
        g_sum1[j] = 0.f; g_sq1[j] = 0.f;
        g_sum2[j] = 0.f; g_sq2[j] = 0.f;
    }
}

// 64x64 fp32 GEMM tile into dynamic smem
template <bool ADD_A>
__device__ __noinline__ void wx_tile(char* sm, const float* A, const float* B,
                                     float* Cf, int bm, int bn) {
    float* As = (float*)sm;            // [16][64]
    float* Bs = As + 16 * 64;          // [16][68]
    int tx = threadIdx.x & 15, ty = threadIdx.x >> 4;
    int r = threadIdx.x >> 2, c4 = (threadIdx.x & 3) * 4;
    int rb = threadIdx.x >> 4, cb = (threadIdx.x & 15) * 4;
    float acc[4][4] = {};
    float4 av = *(const float4*)(A + (bm + r) * 256 + c4);
    float4 bv = *(const float4*)(B + rb * 256 + bn + cb);
    for (int kt = 0; kt < 256; kt += 16) {
        As[(c4 + 0) * 64 + r] = av.x; As[(c4 + 1) * 64 + r] = av.y;
        As[(c4 + 2) * 64 + r] = av.z; As[(c4 + 3) * 64 + r] = av.w;
        *(float4*)&Bs[rb * 68 + cb] = bv;
        __syncthreads();
        if (kt < 240) {
            av = *(const float4*)(A + (bm + r) * 256 + kt + 16 + c4);
            bv = *(const float4*)(B + (kt + 16 + rb) * 256 + bn + cb);
        }
#pragma unroll
        for (int k = 0; k < 16; k++) {
            float a[4], b[4];
#pragma unroll
            for (int i = 0; i < 4; i++) a[i] = As[k * 64 + ty * 4 + i];
#pragma unroll
            for (int j = 0; j < 4; j++) b[j] = Bs[k * 68 + tx * 4 + j];
#pragma unroll
            for (int i = 0; i < 4; i++)
#pragma unroll
                for (int j = 0; j < 4; j++) acc[i][j] = fmaf(a[i], b[j], acc[i][j]);
        }
        __syncthreads();
    }
#pragma unroll
    for (int i = 0; i < 4; i++) {
        int k = bm + ty * 4 + i;
#pragma unroll
        for (int j = 0; j < 4; j++)
            Cf[k * 256 + bn + tx * 4 + j] = acc[i][j] + (ADD_A ? A[k * 256 + bn + tx * 4 + j] : 0.f);
    }
}

// transpose-split one 64x64 tile of W[k][n] into Bo[n][512]
__device__ __noinline__ void split_tile(char* sm, const float* W, __half* Bo,
                                        bool addI, int t) {
    float* T = (float*)sm;   // [64][65]
    int kt = (t & 3) * 64, nt = (t >> 2) * 64;
    int r4 = threadIdx.x >> 6, c = threadIdx.x & 63;
#pragma unroll
    for (int i = 0; i < 16; i++) {
        int row = i * 4 + r4;
        float w = W[(kt + row) * 256 + nt + c];
        if (addI && (kt + row) == (nt + c)) w += 1.f;
        T[row * 65 + c] = w;
    }
    __syncthreads();
#pragma unroll
    for (int i = 0; i < 16; i++) {
        int nl = i * 4 + r4;
        __half h, l;
        split1h(T[c * 65 + nl], h, l);
        Bo[(nt + nl) * 512 + kt + c]       = h;
        Bo[(nt + nl) * 512 + 256 + kt + c] = l;
    }
    __syncthreads();
}

// scaled transpose-split (BN fold): Bo tile from sc[k]*W[k][n]
__device__ __noinline__ void split_tile_sc(char* sm, const float* W, __half* Bo,
                                           const float* sums, const float* sqs,
                                           const float* gamma, int t) {
    const float inv_n = 1.f / (float)N_NODES;
    float* T = (float*)sm;              // [64][65]
    float* sc = T + 64 * 65;
    int kt = (t & 3) * 64, nt = (t >> 2) * 64;
    if (threadIdx.x < 64) {
        int k = kt + threadIdx.x;
        float mu = __ldcg(sums + k) * inv_n;
        float var = __ldcg(sqs + k) * inv_n - mu * mu;
        sc[threadIdx.x] = rsqrtf(var + BN_EPS) * gamma[k];
    }
    __syncthreads();
    int r4 = threadIdx.x >> 6, c = threadIdx.x & 63;
#pragma unroll
    for (int i = 0; i < 16; i++) {
        int row = i * 4 + r4;
        T[row * 65 + c] = sc[row] * W[(kt + row) * 256 + nt + c];
    }
    __syncthreads();
#pragma unroll
    for (int i = 0; i < 16; i++) {
        int nl = i * 4 + r4;
        __half h, l;
        split1h(T[c * 65 + nl], h, l);
        Bo[(nt + nl) * 512 + kt + c]       = h;
        Bo[(nt + nl) * 512 + 256 + kt + c] = l;
    }
    __syncthreads();
}

// single-CTA scan over g_deg (smem-resident), writes g_off/g_cur
__device__ __noinline__ void scan256(char* sm) {
    int* sd = (int*)sm;                 // 16384 ints
    int* ps = sd + 16384;               // 256 partials
    int t = threadIdx.x;
    for (int i = t; i < N_NODES; i += 256) sd[i] = g_deg[i];
    __syncthreads();
    int base = t * 64;
    int sum = 0;
#pragma unroll 8
    for (int i = 0; i < 64; i++) sum += sd[base + i];
    ps[t] = sum;
    __syncthreads();
    for (int d = 1; d < 256; d <<= 1) {
        int v = (t >= d) ? ps[t - d] : 0;
        __syncthreads();
        if (t >= d) ps[t] += v;
        __syncthreads();
    }
    int run = (t == 0) ? 0 : ps[t - 1];
#pragma unroll 8
    for (int i = 0; i < 64; i++) {
        int v = sd[base + i];
        g_off[base + i] = run;
        g_cur[base + i] = run;
        run += v;
    }
    if (t == 255) g_off[N_NODES] = run;
    __syncthreads();
}

// spmm unit u in [0,8192)
__device__ void spmm_unit(int u, const float* eb1, const float* eb2) {
    int layer = u >> 12;
    const __half* ew = layer ? g_ew2h : g_ew1h;
    const float* eb = layer ? eb2 : eb1;
    __half* eo = layer ? g_e2 : g_e;
    int node = (u & 4095) * 4 + (threadIdx.x >> 6);
    int c = threadIdx.x & 63;
    const uint2* ew4 = (const uint2*)ew;
    float4 acc = ((const float4*)eb)[c];
    int s = g_off[node];
    int e = g_off[node + 1];
    for (int k = s; k < e; k++) {
        int j = g_csr[k];
        uint2 v = ew4[j * 64 + c];
        float2 f0 = __half22float2(*(const __half2*)&v.x);
        float2 f1 = __half22float2(*(const __half2*)&v.y);
        acc.x += f0.x; acc.y += f0.y; acc.z += f1.x; acc.w += f1.y;
    }
    ((uint2*)eo)[node * 64 + c] = pack4h(acc);
}

// ================= HMMA fp16 2-term GEMM phase ==============================
#define STAGES   3
#define BUF_SZ   32768
#define STATS_OFF (STAGES * BUF_SZ)
#define SMEM_MMA (STATS_OFF + 1024)

template <int MODE, bool F32S, bool HST, bool XCOPY>
__device__ __noinline__ void gemm_phase(char* smem, int cta,
        const __half* A, const __half* A2,
        const __half* Bb, const __half* B2b,
        const float* bias,
        float* outf, int ldout, __half* oh,
        float* sumP, float* sqP, const float* xsrc) {
    const unsigned sbase = smem_u32(smem);
    const int tid = threadIdx.x;
    const int lane = tid & 31;
    const int w = tid >> 5;
    const int wm = w & 3;
    const int wn = w >> 2;
    const int bm = (cta >> 1) * 128;
    const int bn = (cta & 1) * 128;

    const int NC = (MODE == 1) ? 16 : 8;

    auto issue = [&](int c) {
        const bool second = (MODE == 1) && (c >= 8);
        const int local = second ? c - 8 : c;
        const __half* Ap = second ? A2 : A;
        const __half* Bp = second ? B2b : Bb;
        const int ka = (local & 3) << 6;
        const int kb = local << 6;
        const unsigned sa = sbase + (c % STAGES) * BUF_SZ;
        const unsigned sb = sa + 16384;
#pragma unroll
        for (int i = 0; i < 4; i++) {
            int u = tid + (i << 8);
            int row = u >> 3, seg = u & 7;
            cp16(sa + row * 128 + ((seg ^ (row & 7)) << 4),
                 Ap + ((bm + row) << 8) + ka + (seg << 3));
        }
#pragma unroll
        for (int i = 0; i < 4; i++) {
            int u = tid + (i << 8);
            int row = u >> 3, seg = u & 7;
            cp16(sb + row * 128 + ((seg ^ (row & 7)) << 4),
                 Bp + (bn + row) * 512 + kb + (seg << 3));
        }
        cp_commit();
    };

    const int a_row = wm * 32 + (lane & 15);
    const int a_kh = lane >> 4;
    const int b_nrel = ((lane >> 4) << 3) + (lane & 7);
    const int b_n = wn * 64 + b_nrel;
    const int b_kh = (lane >> 3) & 1;

    float acc[2][8][4];
#pragma unroll
    for (int mt = 0; mt < 2; mt++)
#pragma unroll
        for (int nt = 0; nt < 8; nt++)
#pragma unroll
            for (int q = 0; q < 4; q++) acc[mt][nt][q] = 0.f;

    issue(0); issue(1); issue(2);

    for (int c = 0; c < NC; c++) {
        if (c >= NC - 2) cp_wait<0>(); else cp_wait<STAGES - 1>();
        __syncthreads();
        const unsigned sa = sbase + (c % STAGES) * BUF_SZ;
        const unsigned sb = sa + 16384;
#pragma unroll
        for (int ks = 0; ks < 4; ks++) {
            const int seg0 = ks * 2;
            unsigned af[2][4];
#pragma unroll
            for (int mt = 0; mt < 2; mt++) {
                int r = a_row + mt * 16;
                ldsm_x4(af[mt], sa + r * 128 + (((seg0 + a_kh) ^ (r & 7)) << 4));
            }
            unsigned bf[8][2];
#pragma unroll
            for (int np = 0; np < 4; np++) {
                int n = b_n + np * 16;
                unsigned t4[4];
                ldsm_x4(t4, sb + n * 128 + (((seg0 + b_kh) ^ (n & 7)) << 4));
                bf[np * 2][0] = t4[0]; bf[np * 2][1] = t4[1];
                bf[np * 2 + 1][0] = t4[2]; bf[np * 2 + 1][1] = t4[3];
            }
#pragma unroll
            for (int mt = 0; mt < 2; mt++)
#pragma unroll
                for (int nt = 0; nt < 8; nt++)
                    mma_fp16(acc[mt][nt], af[mt], bf[nt]);
        }
        __syncthreads();
        if (c + STAGES < NC) issue(c + STAGES);
    }
    __syncthreads();

    // epilogue: regs -> staged fp32 tile
    const int er = lane >> 2;
    const int ec = (lane & 3) << 1;
#pragma unroll
    for (int mt = 0; mt < 2; mt++) {
#pragma unroll
        for (int nt = 0; nt < 8; nt++) {
            int r0 = wm * 32 + mt * 16 + er;
            int cc = wn * 64 + nt * 8 + ec;
            float b0 = __ldcg(bias + bn + cc), b1 = __ldcg(bias + bn + cc + 1);
            float v0 = acc[mt][nt][0] + b0, v1 = acc[mt][nt][1] + b1;
            float v2 = acc[mt][nt][2] + b0, v3 = acc[mt][nt][3] + b1;
            if (MODE == 1 || MODE == 2) {
                v0 = fmaxf(v0, 0.f); v1 = fmaxf(v1, 0.f);
                v2 = fmaxf(v2, 0.f); v3 = fmaxf(v3, 0.f);
            }
            int r1 = r0 + 8;
            *(float2*)(smem + r0 * 512 + ((((cc >> 2) ^ ((r0 & 7) << 2))) << 4) + ((cc & 3) << 2)) = make_float2(v0, v1);
            *(float2*)(smem + r1 * 512 + ((((cc >> 2) ^ ((r1 & 7) << 2))) << 4) + ((cc & 3) << 2)) = make_float2(v2, v3);
        }
    }
    __syncthreads();

    // staged -> global
#pragma unroll 4
    for (int i = 0; i < 16; i++) {
        int u = tid + (i << 8);
        int r = u >> 5, seg = u & 31;
        float4 v = *(const float4*)(smem + r * 512 + ((seg ^ ((r & 7) << 2)) << 4));
        int grow = bm + r;
        int gcol = bn + (seg << 2);
        if (F32S) {
            *(float4*)(outf + grow * ldout + gcol) = v;
            if (XCOPY) {
                float4 xv = ((const float4*)xsrc)[(grow << 6) + (gcol >> 2)];
                *(float4*)(outf + grow * ldout + 256 + gcol) = xv;
            }
        }
        if (HST)  ((uint2*)oh)[(grow << 6) + (gcol >> 2)] = pack4h(v);
    }

    // BN stats
    if (MODE == 2) {
        int c = tid & 127, r0 = (tid >> 7) << 6;
        float s = 0.f, q = 0.f;
#pragma unroll 4
        for (int rr = 0; rr < 64; rr++) {
            int r = r0 + rr;
            float v = *(const float*)(smem + r * 512 +
                                      ((((c >> 2) ^ ((r & 7) << 2))) << 4) + ((c & 3) << 2));
            s += v;
            q += v * v;
        }
        float* st = (float*)(smem + STATS_OFF);
        __syncthreads();
        if (tid >= 128) { st[c] = s; st[128 + c] = q; }
        __syncthreads();
        if (tid < 128) {
            atomicAdd(&sumP[bn + c], s + st[c]);
            atomicAdd(&sqP [bn + c], q + st[128 + c]);
        }
    }
    __syncthreads();
}

// ================= the mega kernel ==========================================
struct Params {
    const float* x;
    const int* ei;
    const float* P1[14];
    const float* P2[14];
    float* out;
};

__global__ __launch_bounds__(256, 2) void mega_k(Params P) {
    extern __shared__ char smem[];
    const int cta = blockIdx.x;
    unsigned gen = __ldcg(&g_flags[cta]);

    // ---- P0: conversions + zero deg/stats; wx2 & wx1 tiles ----
    for (unsigned u = cta; u < 12353u; u += 256)
        conv_unit(u, P.x, P.P1[0], P.P2[0]);
    if (cta < 16)
        wx_tile<true>(smem, P.P2[2], P.P2[6], g_wx2, (cta >> 2) * 64, (cta & 3) * 64);
    else if (cta < 32)
        wx_tile<true>(smem, P.P1[2], P.P1[6], g_wx1, ((cta - 16) >> 2) * 64, ((cta - 16) & 3) * 64);
    grid_bar(++gen);

    // ---- P1: hist || G tiles || splitw tiles || biasr1 ----
    if (cta < 16) {
        wx_tile<false>(smem, P.P1[12], g_wx2, g_G, (cta >> 2) * 64, (cta & 3) * 64);
    } else if (cta < 96) {
        int b = cta - 16;          // 0..79
        int mat = b >> 4, t = b & 15;
        const float* W;
        __half* B;
        bool addI = false;
        switch (mat) {
            case 0: W = P.P1[4]; B = g_Bw1a; addI = true; break;
            case 1: W = P.P1[8]; B = g_Bf1a; break;
            case 2: W = P.P2[4]; B = g_Bw1b; addI = true; break;
            case 3: W = P.P2[8]; B = g_Bf1b; break;
            default: W = g_wx1;  B = g_Bwx; break;
        }
        split_tile(smem, W, B, addI, t);
    } else if (cta == 96) {
        int n = threadIdx.x;
        float s = P.P1[5][n] + P.P1[7][n] + P.P1[3][n];
        for (int k = 0; k < 256; k++) s += P.P1[3][k] * P.P1[6][k * 256 + n];
        g_biasr[n] = s;
    } else {
        for (int u = cta - 97; u < 1024; u += 159) {
            int e = u * 256 + threadIdx.x;
            atomicAdd(&g_deg[P.ei[N_EDGES + e]], 1);
        }
    }
    grid_bar(++gen);

    // ---- P2: scan (CTA 0 only) ----
    if (cta == 0) scan256(smem);
    grid_bar(++gen);

    // ---- P3: scatter ----
    for (int u = cta; u < 1024; u += 256) {
        int e = u * 256 + threadIdx.x;
        int d = P.ei[N_EDGES + e];
        int p = atomicAdd(&g_cur[d], 1);
        g_csr[p] = P.ei[e];
    }
    grid_bar(++gen);

    // ---- P4: spmm both layers ----
    for (int u = cta; u < 8192; u += 256)
        spmm_unit(u, P.P1[1], P.P2[1]);
    grid_bar(++gen);

    // ---- P5: r1 = relu(emb1@(I+c1w1) + x@wx1 + biasr1) ----
    gemm_phase<1, false, true, false>(smem, cta, g_e, g_x, g_Bw1a, g_Bwx,
                                      g_biasr, nullptr, 0, g_r,
                                      nullptr, nullptr, nullptr);
    grid_bar(++gen);

    // ---- P6: q1 = relu(r1@f1w1 + f1b1), stats1 ----
    gemm_phase<2, false, true, false>(smem, cta, g_r, nullptr, g_Bf1a, nullptr,
                                      P.P1[9], nullptr, 0, g_q,
                                      g_sum1, g_sq1, nullptr);
    grid_bar(++gen);

    // ---- P7: B2 = diag(s1)@G tiles ; biasr = layer2 fused bias ----
    if (cta < 16) {
        split_tile_sc(smem, g_G, g_B2, g_sum1, g_sq1, P.P1[10], cta);
    } else if (cta == 16) {
        const float inv_n = 1.f / (float)N_NODES;
        int n = threadIdx.x;
        float s = P.P2[5][n] + P.P2[7][n] + P.P2[3][n];
        for (int k = 0; k < 256; k++) {
            float mu = __ldcg(g_sum1 + k) * inv_n;
            float var = __ldcg(g_sq1 + k) * inv_n - mu * mu;
            float rs = rsqrtf(var + BN_EPS);
            float t1 = P.P1[11][k] - mu * rs * P.P1[10][k];
            s += P.P2[3][k] * P.P2[6][k * 256 + n] + t1 * g_G[(k << 8) + n]
               + P.P1[13][k] * g_wx2[(k << 8) + n];
        }
        g_biasr[n] = s;
    }
    grid_bar(++gen);

    // ---- P8: r2 = relu(emb2@(I+c1w2) + q1@B2 + biasr2) ----
    gemm_phase<1, false, true, false>(smem, cta, g_e2, g_q, g_Bw1b, g_B2,
                                      g_biasr, nullptr, 0, g_r,
                                      nullptr, nullptr, nullptr);
    grid_bar(++gen);

    // ---- P9: q2 = relu(r2@f1w2 + f1b2), stats2 ----
    gemm_phase<2, false, true, false>(smem, cta, g_r, nullptr, g_Bf1b, nullptr,
                                      P.P2[9], nullptr, 0, g_q,
                                      g_sum2, g_sq2, nullptr);
    grid_bar(++gen);

    // ---- P10: Bf2 = diag(s2)@f2w2 tiles ; bias3 ----
    if (cta < 16) {
        split_tile_sc(smem, P.P2[12], g_Bf2, g_sum2, g_sq2, P.P2[10], cta);
    } else if (cta == 16) {
        const float inv_n = 1.f / (float)N_NODES;
        int n = threadIdx.x;
        float s = P.P2[13][n];
        for (int k = 0; k < 256; k++) {
            float mu = __ldcg(g_sum2 + k) * inv_n;
            float var = __ldcg(g_sq2 + k) * inv_n - mu * mu;
            float rs = rsqrtf(var + BN_EPS);
            s += (P.P2[11][k] - mu * rs * P.P2[10][k]) * P.P2[12][(k << 8) + n];
        }
        g_bias3[n] = s;
    }
    grid_bar(++gen);

    // ---- P11: out[:,0:256] = (q2*s2+t2)@f2w2 + f2b2 ; out[:,256:512] = x ----
    gemm_phase<3, true, false, true>(smem, cta, g_q, nullptr, g_Bf2, nullptr,
                                     g_bias3, P.out, 512, nullptr,
                                     nullptr, nullptr, P.x);
}

// ================= host orchestration ========================================
extern "C" void kernel_launch(void* const* d_in, const int* in_sizes, int n_in,
                              void* d_out, int out_size) {
    (void)in_sizes; (void)n_in; (void)out_size;

    Params P;
    P.x  = (const float*)d_in[0];
    P.ei = (const int*)d_in[2];
    for (int i = 0; i < 14; i++) {
        P.P1[i] = (const float*)d_in[4 + i];
        P.P2[i] = (const float*)d_in[18 + i];
    }
    P.out = (float*)d_out;

    cudaFuncSetAttribute(mega_k, cudaFuncAttributeMaxDynamicSharedMemorySize,
                         SMEM_MMA);

    mega_k<<<256, 256, SMEM_MMA>>>(P);
}

// round 14
// speedup vs baseline: 1.1771x; 1.0318x over previous
#include <cuda_runtime.h>
#include <cuda_fp16.h>

#define N_NODES 16384
#define N_EDGES 262144
#define D_CH    256
#define BN_EPS  1e-5f

// ================= device scratch (no runtime allocation) ==================
__device__ __half g_x [N_NODES * D_CH];
__device__ __half g_e [N_NODES * D_CH];
__device__ __half g_e2[N_NODES * D_CH];
__device__ __half g_r [N_NODES * D_CH];
__device__ __half g_q [N_NODES * D_CH];

__device__ __half g_ew1h[N_NODES * D_CH];
__device__ __half g_ew2h[N_NODES * D_CH];

// stacked split weights, [N=256 rows][K'=512]: [hi(256) | lo(256)]
__device__ __half g_Bw1a[D_CH * 512];
__device__ __half g_Bf1a[D_CH * 512];
__device__ __half g_Bw1b[D_CH * 512];
__device__ __half g_Bf1b[D_CH * 512];
__device__ __half g_Bwx [D_CH * 512];
__device__ __half g_B2  [D_CH * 512];
__device__ __half g_Bf2 [D_CH * 512];

__device__ float g_wx1[D_CH * D_CH];
__device__ float g_wx2[D_CH * D_CH];
__device__ float g_G  [D_CH * D_CH];

__device__ float g_biasr[D_CH];
__device__ float g_bias3[D_CH];

__device__ float g_sum1[D_CH];
__device__ float g_sq1 [D_CH];
__device__ float g_sum2[D_CH];
__device__ float g_sq2 [D_CH];

__device__ int g_deg[N_NODES];       // zeroed at end of each run (P2)
__device__ int g_off[N_NODES + 1];
__device__ int g_cur[N_NODES];
__device__ int g_csr[N_EDGES];

__device__ unsigned g_flags[256];    // grid barrier flags (monotone gens)

// ================= PTX helpers ==============================================
__device__ __forceinline__ unsigned smem_u32(const void* p) {
    unsigned a;
    asm("{ .reg .u64 t; cvta.to.shared.u64 t, %1; cvt.u32.u64 %0, t; }"
        : "=r"(a) : "l"(p));
    return a;
}
__device__ __forceinline__ void cp16(unsigned dst, const void* src) {
    asm volatile("cp.async.cg.shared.global [%0], [%1], 16;"
                 :: "r"(dst), "l"(src) : "memory");
}
__device__ __forceinline__ void cp_commit() {
    asm volatile("cp.async.commit_group;" ::: "memory");
}
template <int N>
__device__ __forceinline__ void cp_wait() {
    asm volatile("cp.async.wait_group %0;" :: "n"(N) : "memory");
}
__device__ __forceinline__ void ldsm_x4(unsigned* r, unsigned addr) {
    asm volatile("ldmatrix.sync.aligned.m8n8.x4.shared.b16 {%0,%1,%2,%3}, [%4];"
                 : "=r"(r[0]), "=r"(r[1]), "=r"(r[2]), "=r"(r[3]) : "r"(addr));
}
__device__ __forceinline__ void mma_fp16(float* c, const unsigned* a, const unsigned* b) {
    asm volatile(
        "mma.sync.aligned.m16n8k16.row.col.f32.f16.f16.f32 "
        "{%0,%1,%2,%3}, {%4,%5,%6,%7}, {%8,%9}, {%0,%1,%2,%3};"
        : "+f"(c[0]), "+f"(c[1]), "+f"(c[2]), "+f"(c[3])
        : "r"(a[0]), "r"(a[1]), "r"(a[2]), "r"(a[3]), "r"(b[0]), "r"(b[1]));
}
__device__ __forceinline__ void split1h(float v, __half& h, __half& l) {
    h = __float2half_rn(v);
    l = __float2half_rn(v - __half2float(h));
}
__device__ __forceinline__ uint2 pack4h(float4 v) {
    __half2 a = __floats2half2_rn(v.x, v.y);
    __half2 b = __floats2half2_rn(v.z, v.w);
    uint2 r;
    r.x = *(unsigned*)&a;
    r.y = *(unsigned*)&b;
    return r;
}

// ================= grid barrier =============================================
__device__ __forceinline__ void grid_bar(unsigned gen) {
    __syncthreads();
    __threadfence();
    if (threadIdx.x == 0) atomicExch(&g_flags[blockIdx.x], gen);
    for (;;) {
        unsigned v = __ldcg(&g_flags[threadIdx.x]);
        if (__syncthreads_and((int)(v - gen) >= 0)) break;
        __nanosleep(128);
    }
    __threadfence();
}

// ================= phase pieces ==============================================
// conv unit: u in [0,12289): x(4096) | ew1(4096) | ew2(4096) | stats(1)
__device__ void conv_unit(unsigned u, const float* x, const float* ew1,
                          const float* ew2) {
    if (u < 4096) {
        int i = u * 256 + threadIdx.x;
        ((uint2*)g_x)[i] = pack4h(((const float4*)x)[i]);
    } else if (u < 8192) {
        int i = (u - 4096) * 256 + threadIdx.x;
        ((uint2*)g_ew1h)[i] = pack4h(((const float4*)ew1)[i]);
    } else if (u < 12288) {
        int i = (u - 8192) * 256 + threadIdx.x;
        ((uint2*)g_ew2h)[i] = pack4h(((const float4*)ew2)[i]);
    } else {
        int j = threadIdx.x;
        g_sum1[j] = 0.f; g_sq1[j] = 0.f;
        g_sum2[j] = 0.f; g_sq2[j] = 0.f;
    }
}

// 64x64 fp32 GEMM tile into dynamic smem
template <bool ADD_A>
__device__ __noinline__ void wx_tile(char* sm, const float* A, const float* B,
                                     float* Cf, int bm, int bn) {
    float* As = (float*)sm;            // [16][64]
    float* Bs = As + 16 * 64;          // [16][68]
    int tx = threadIdx.x & 15, ty = threadIdx.x >> 4;
    int r = threadIdx.x >> 2, c4 = (threadIdx.x & 3) * 4;
    int rb = threadIdx.x >> 4, cb = (threadIdx.x & 15) * 4;
    float acc[4][4] = {};
    float4 av = *(const float4*)(A + (bm + r) * 256 + c4);
    float4 bv = *(const float4*)(B + rb * 256 + bn + cb);
    for (int kt = 0; kt < 256; kt += 16) {
        As[(c4 + 0) * 64 + r] = av.x; As[(c4 + 1) * 64 + r] = av.y;
        As[(c4 + 2) * 64 + r] = av.z; As[(c4 + 3) * 64 + r] = av.w;
        *(float4*)&Bs[rb * 68 + cb] = bv;
        __syncthreads();
        if (kt < 240) {
            av = *(const float4*)(A + (bm + r) * 256 + kt + 16 + c4);
            bv = *(const float4*)(B + (kt + 16 + rb) * 256 + bn + cb);
        }
#pragma unroll
        for (int k = 0; k < 16; k++) {
            float a[4], b[4];
#pragma unroll
            for (int i = 0; i < 4; i++) a[i] = As[k * 64 + ty * 4 + i];
#pragma unroll
            for (int j = 0; j < 4; j++) b[j] = Bs[k * 68 + tx * 4 + j];
#pragma unroll
            for (int i = 0; i < 4; i++)
#pragma unroll
                for (int j = 0; j < 4; j++) acc[i][j] = fmaf(a[i], b[j], acc[i][j]);
        }
        __syncthreads();
    }
#pragma unroll
    for (int i = 0; i < 4; i++) {
        int k = bm + ty * 4 + i;
#pragma unroll
        for (int j = 0; j < 4; j++)
            Cf[k * 256 + bn + tx * 4 + j] = acc[i][j] + (ADD_A ? A[k * 256 + bn + tx * 4 + j] : 0.f);
    }
    __syncthreads();
}

// transpose-split one 64x64 tile of W[k][n] into Bo[n][512]
__device__ __noinline__ void split_tile(char* sm, const float* W, __half* Bo,
                                        bool addI, int t) {
    float* T = (float*)sm;   // [64][65]
    int kt = (t & 3) * 64, nt = (t >> 2) * 64;
    int r4 = threadIdx.x >> 6, c = threadIdx.x & 63;
#pragma unroll
    for (int i = 0; i < 16; i++) {
        int row = i * 4 + r4;
        float w = W[(kt + row) * 256 + nt + c];
        if (addI && (kt + row) == (nt + c)) w += 1.f;
        T[row * 65 + c] = w;
    }
    __syncthreads();
#pragma unroll
    for (int i = 0; i < 16; i++) {
        int nl = i * 4 + r4;
        __half h, l;
        split1h(T[c * 65 + nl], h, l);
        Bo[(nt + nl) * 512 + kt + c]       = h;
        Bo[(nt + nl) * 512 + 256 + kt + c] = l;
    }
    __syncthreads();
}

// scaled transpose-split (BN fold)
__device__ __noinline__ void split_tile_sc(char* sm, const float* W, __half* Bo,
                                           const float* sums, const float* sqs,
                                           const float* gamma, int t) {
    const float inv_n = 1.f / (float)N_NODES;
    float* T = (float*)sm;
    float* sc = T + 64 * 65;
    int kt = (t & 3) * 64, nt = (t >> 2) * 64;
    if (threadIdx.x < 64) {
        int k = kt + threadIdx.x;
        float mu = __ldcg(sums + k) * inv_n;
        float var = __ldcg(sqs + k) * inv_n - mu * mu;
        sc[threadIdx.x] = rsqrtf(var + BN_EPS) * gamma[k];
    }
    __syncthreads();
    int r4 = threadIdx.x >> 6, c = threadIdx.x & 63;
#pragma unroll
    for (int i = 0; i < 16; i++) {
        int row = i * 4 + r4;
        T[row * 65 + c] = sc[row] * W[(kt + row) * 256 + nt + c];
    }
    __syncthreads();
#pragma unroll
    for (int i = 0; i < 16; i++) {
        int nl = i * 4 + r4;
        __half h, l;
        split1h(T[c * 65 + nl], h, l);
        Bo[(nt + nl) * 512 + kt + c]       = h;
        Bo[(nt + nl) * 512 + 256 + kt + c] = l;
    }
    __syncthreads();
}

// single-CTA scan over g_deg (smem-resident)
__device__ __noinline__ void scan256(char* sm) {
    int* sd = (int*)sm;
    int* ps = sd + 16384;
    int t = threadIdx.x;
    for (int i = t; i < N_NODES; i += 256) sd[i] = g_deg[i];
    __syncthreads();
    int base = t * 64;
    int sum = 0;
#pragma unroll 8
    for (int i = 0; i < 64; i++) sum += sd[base + i];
    ps[t] = sum;
    __syncthreads();
    for (int d = 1; d < 256; d <<= 1) {
        int v = (t >= d) ? ps[t - d] : 0;
        __syncthreads();
        if (t >= d) ps[t] += v;
        __syncthreads();
    }
    int run = (t == 0) ? 0 : ps[t - 1];
#pragma unroll 8
    for (int i = 0; i < 64; i++) {
        int v = sd[base + i];
        g_off[base + i] = run;
        g_cur[base + i] = run;
        run += v;
    }
    if (t == 255) g_off[N_NODES] = run;
    __syncthreads();
}

// merged spmm: one CSR traversal, both layers. u in [0,4096)
__device__ void spmm_unit2(int u, const float* eb1, const float* eb2) {
    int node = u * 4 + (threadIdx.x >> 6);
    int c = threadIdx.x & 63;
    const uint2* w1 = (const uint2*)g_ew1h;
    const uint2* w2 = (const uint2*)g_ew2h;
    float4 a1 = ((const float4*)eb1)[c];
    float4 a2 = ((const float4*)eb2)[c];
    int s = g_off[node];
    int e = g_off[node + 1];
    for (int k = s; k < e; k++) {
        int j = g_csr[k] * 64 + c;
        uint2 v1 = w1[j];
        uint2 v2 = w2[j];
        float2 p0 = __half22float2(*(const __half2*)&v1.x);
        float2 p1 = __half22float2(*(const __half2*)&v1.y);
        a1.x += p0.x; a1.y += p0.y; a1.z += p1.x; a1.w += p1.y;
        float2 q0 = __half22float2(*(const __half2*)&v2.x);
        float2 q1 = __half22float2(*(const __half2*)&v2.y);
        a2.x += q0.x; a2.y += q0.y; a2.z += q1.x; a2.w += q1.y;
    }
    ((uint2*)g_e)[node * 64 + c]  = pack4h(a1);
    ((uint2*)g_e2)[node * 64 + c] = pack4h(a2);
}

// ================= HMMA fp16 2-term GEMM phase ==============================
#define STAGES   3
#define BUF_SZ   32768
#define STATS_OFF (STAGES * BUF_SZ)
#define SMEM_MMA (STATS_OFF + 1024)

template <int MODE, bool F32S, bool HST, bool XCOPY>
__device__ __noinline__ void gemm_phase(char* smem, int cta,
        const __half* A, const __half* A2,
        const __half* Bb, const __half* B2b,
        const float* bias,
        float* outf, int ldout, __half* oh,
        float* sumP, float* sqP, const float* xsrc) {
    const unsigned sbase = smem_u32(smem);
    const int tid = threadIdx.x;
    const int lane = tid & 31;
    const int w = tid >> 5;
    const int wm = w & 3;
    const int wn = w >> 2;
    const int bm = (cta >> 1) * 128;
    const int bn = (cta & 1) * 128;

    const int NC = (MODE == 1) ? 16 : 8;

    auto issue = [&](int c) {
        const bool second = (MODE == 1) && (c >= 8);
        const int local = second ? c - 8 : c;
        const __half* Ap = second ? A2 : A;
        const __half* Bp = second ? B2b : Bb;
        const int ka = (local & 3) << 6;
        const int kb = local << 6;
        const unsigned sa = sbase + (c % STAGES) * BUF_SZ;
        const unsigned sb = sa + 16384;
#pragma unroll
        for (int i = 0; i < 4; i++) {
            int u = tid + (i << 8);
            int row = u >> 3, seg = u & 7;
            cp16(sa + row * 128 + ((seg ^ (row & 7)) << 4),
                 Ap + ((bm + row) << 8) + ka + (seg << 3));
        }
#pragma unroll
        for (int i = 0; i < 4; i++) {
            int u = tid + (i << 8);
            int row = u >> 3, seg = u & 7;
            cp16(sb + row * 128 + ((seg ^ (row & 7)) << 4),
                 Bp + (bn + row) * 512 + kb + (seg << 3));
        }
        cp_commit();
    };

    const int a_row = wm * 32 + (lane & 15);
    const int a_kh = lane >> 4;
    const int b_nrel = ((lane >> 4) << 3) + (lane & 7);
    const int b_n = wn * 64 + b_nrel;
    const int b_kh = (lane >> 3) & 1;

    float acc[2][8][4];
#pragma unroll
    for (int mt = 0; mt < 2; mt++)
#pragma unroll
        for (int nt = 0; nt < 8; nt++)
#pragma unroll
            for (int q = 0; q < 4; q++) acc[mt][nt][q] = 0.f;

    issue(0); issue(1); issue(2);

    for (int c = 0; c < NC; c++) {
        if (c >= NC - 2) cp_wait<0>(); else cp_wait<STAGES - 1>();
        __syncthreads();
        const unsigned sa = sbase + (c % STAGES) * BUF_SZ;
        const unsigned sb = sa + 16384;
#pragma unroll
        for (int ks = 0; ks < 4; ks++) {
            const int seg0 = ks * 2;
            unsigned af[2][4];
#pragma unroll
            for (int mt = 0; mt < 2; mt++) {
                int r = a_row + mt * 16;
                ldsm_x4(af[mt], sa + r * 128 + (((seg0 + a_kh) ^ (r & 7)) << 4));
            }
            unsigned bf[8][2];
#pragma unroll
            for (int np = 0; np < 4; np++) {
                int n = b_n + np * 16;
                unsigned t4[4];
                ldsm_x4(t4, sb + n * 128 + (((seg0 + b_kh) ^ (n & 7)) << 4));
                bf[np * 2][0] = t4[0]; bf[np * 2][1] = t4[1];
                bf[np * 2 + 1][0] = t4[2]; bf[np * 2 + 1][1] = t4[3];
            }
#pragma unroll
            for (int mt = 0; mt < 2; mt++)
#pragma unroll
                for (int nt = 0; nt < 8; nt++)
                    mma_fp16(acc[mt][nt], af[mt], bf[nt]);
        }
        __syncthreads();
        if (c + STAGES < NC) issue(c + STAGES);
    }
    __syncthreads();

    // epilogue: regs -> staged fp32 tile
    const int er = lane >> 2;
    const int ec = (lane & 3) << 1;
#pragma unroll
    for (int mt = 0; mt < 2; mt++) {
#pragma unroll
        for (int nt = 0; nt < 8; nt++) {
            int r0 = wm * 32 + mt * 16 + er;
            int cc = wn * 64 + nt * 8 + ec;
            float b0 = __ldcg(bias + bn + cc), b1 = __ldcg(bias + bn + cc + 1);
            float v0 = acc[mt][nt][0] + b0, v1 = acc[mt][nt][1] + b1;
            float v2 = acc[mt][nt][2] + b0, v3 = acc[mt][nt][3] + b1;
            if (MODE == 1 || MODE == 2) {
                v0 = fmaxf(v0, 0.f); v1 = fmaxf(v1, 0.f);
                v2 = fmaxf(v2, 0.f); v3 = fmaxf(v3, 0.f);
            }
            int r1 = r0 + 8;
            *(float2*)(smem + r0 * 512 + ((((cc >> 2) ^ ((r0 & 7) << 2))) << 4) + ((cc & 3) << 2)) = make_float2(v0, v1);
            *(float2*)(smem + r1 * 512 + ((((cc >> 2) ^ ((r1 & 7) << 2))) << 4) + ((cc & 3) << 2)) = make_float2(v2, v3);
        }
    }
    __syncthreads();

    // staged -> global
#pragma unroll 4
    for (int i = 0; i < 16; i++) {
        int u = tid + (i << 8);
        int r = u >> 5, seg = u & 31;
        float4 v = *(const float4*)(smem + r * 512 + ((seg ^ ((r & 7) << 2)) << 4));
        int grow = bm + r;
        int gcol = bn + (seg << 2);
        if (F32S) {
            *(float4*)(outf + grow * ldout + gcol) = v;
            if (XCOPY) {
                float4 xv = ((const float4*)xsrc)[(grow << 6) + (gcol >> 2)];
                *(float4*)(outf + grow * ldout + 256 + gcol) = xv;
            }
        }
        if (HST)  ((uint2*)oh)[(grow << 6) + (gcol >> 2)] = pack4h(v);
    }

    // BN stats
    if (MODE == 2) {
        int c = tid & 127, r0 = (tid >> 7) << 6;
        float s = 0.f, q = 0.f;
#pragma unroll 4
        for (int rr = 0; rr < 64; rr++) {
            int r = r0 + rr;
            float v = *(const float*)(smem + r * 512 +
                                      ((((c >> 2) ^ ((r & 7) << 2))) << 4) + ((c & 3) << 2));
            s += v;
            q += v * v;
        }
        float* st = (float*)(smem + STATS_OFF);
        __syncthreads();
        if (tid >= 128) { st[c] = s; st[128 + c] = q; }
        __syncthreads();
        if (tid < 128) {
            atomicAdd(&sumP[bn + c], s + st[c]);
            atomicAdd(&sqP [bn + c], q + st[128 + c]);
        }
    }
    __syncthreads();
}

// ================= the mega kernel ==========================================
struct Params {
    const float* x;
    const int* ei;
    const float* P1[14];
    const float* P2[14];
    float* out;
};

__global__ __launch_bounds__(256, 2) void mega_k(Params P) {
    extern __shared__ char smem[];
    const int cta = blockIdx.x;
    unsigned gen = __ldcg(&g_flags[cta]);

    // ---- P0: conversions (all CTAs) + wx tiles + hist + biasr1 ----
    // (g_deg is zero: first launch via static init, later via P2 of prior run)
    if (cta < 16) {
        wx_tile<true>(smem, P.P2[2], P.P2[6], g_wx2, (cta >> 2) * 64, (cta & 3) * 64);
    } else if (cta < 32) {
        wx_tile<true>(smem, P.P1[2], P.P1[6], g_wx1, ((cta - 16) >> 2) * 64, ((cta - 16) & 3) * 64);
    } else if (cta == 32) {
        int n = threadIdx.x;
        float s = P.P1[5][n] + P.P1[7][n] + P.P1[3][n];
        for (int k = 0; k < 256; k++) s += P.P1[3][k] * P.P1[6][k * 256 + n];
        g_biasr[n] = s;
    } else if (cta < 97) {
        for (int u = cta - 33; u < 1024; u += 64) {
            int e = u * 256 + threadIdx.x;
            atomicAdd(&g_deg[P.ei[N_EDGES + e]], 1);
        }
    }
    for (unsigned u = cta; u < 12289u; u += 256)
        conv_unit(u, P.x, P.P1[0], P.P2[0]);
    grid_bar(++gen);

    // ---- P1: scan (CTA 0) || G tiles || splitw tiles ----
    if (cta == 0) {
        scan256(smem);
    } else if (cta < 17) {
        wx_tile<false>(smem, P.P1[12], g_wx2, g_G, ((cta - 1) >> 2) * 64, ((cta - 1) & 3) * 64);
    } else if (cta < 97) {
        int b = cta - 17;          // 0..79
        int mat = b >> 4, t = b & 15;
        const float* W;
        __half* B;
        bool addI = false;
        switch (mat) {
            case 0: W = P.P1[4]; B = g_Bw1a; addI = true; break;
            case 1: W = P.P1[8]; B = g_Bf1a; break;
            case 2: W = P.P2[4]; B = g_Bw1b; addI = true; break;
            case 3: W = P.P2[8]; B = g_Bf1b; break;
            default: W = g_wx1;  B = g_Bwx; break;
        }
        split_tile(smem, W, B, addI, t);
    }
    grid_bar(++gen);

    // ---- P2: scatter + zero g_deg for next run ----
    for (int u = cta; u < 1024; u += 256) {
        int e = u * 256 + threadIdx.x;
        int d = P.ei[N_EDGES + e];
        int p = atomicAdd(&g_cur[d], 1);
        g_csr[p] = P.ei[e];
    }
    if (cta < 64) g_deg[cta * 256 + threadIdx.x] = 0;
    grid_bar(++gen);

    // ---- P3: merged spmm (both layers, one traversal) ----
    for (int u = cta; u < 4096; u += 256)
        spmm_unit2(u, P.P1[1], P.P2[1]);
    grid_bar(++gen);

    // ---- P4: r1 = relu(emb1@(I+c1w1) + x@wx1 + biasr1) ----
    gemm_phase<1, false, true, false>(smem, cta, g_e, g_x, g_Bw1a, g_Bwx,
                                      g_biasr, nullptr, 0, g_r,
                                      nullptr, nullptr, nullptr);
    grid_bar(++gen);

    // ---- P5: q1 = relu(r1@f1w1 + f1b1), stats1 ----
    gemm_phase<2, false, true, false>(smem, cta, g_r, nullptr, g_Bf1a, nullptr,
                                      P.P1[9], nullptr, 0, g_q,
                                      g_sum1, g_sq1, nullptr);
    grid_bar(++gen);

    // ---- P6: B2 = diag(s1)@G tiles ; biasr = layer2 fused bias ----
    if (cta < 16) {
        split_tile_sc(smem, g_G, g_B2, g_sum1, g_sq1, P.P1[10], cta);
    } else if (cta == 16) {
        const float inv_n = 1.f / (float)N_NODES;
        int n = threadIdx.x;
        float s = P.P2[5][n] + P.P2[7][n] + P.P2[3][n];
        for (int k = 0; k < 256; k++) {
            float mu = __ldcg(g_sum1 + k) * inv_n;
            float var = __ldcg(g_sq1 + k) * inv_n - mu * mu;
            float rs = rsqrtf(var + BN_EPS);
            float t1 = P.P1[11][k] - mu * rs * P.P1[10][k];
            s += P.P2[3][k] * P.P2[6][k * 256 + n] + t1 * g_G[(k << 8) + n]
               + P.P1[13][k] * g_wx2[(k << 8) + n];
        }
        g_biasr[n] = s;
    }
    grid_bar(++gen);

    // ---- P7: r2 = relu(emb2@(I+c1w2) + q1@B2 + biasr2) ----
    gemm_phase<1, false, true, false>(smem, cta, g_e2, g_q, g_Bw1b, g_B2,
                                      g_biasr, nullptr, 0, g_r,
                                      nullptr, nullptr, nullptr);
    grid_bar(++gen);

    // ---- P8: q2 = relu(r2@f1w2 + f1b2), stats2 ----
    gemm_phase<2, false, true, false>(smem, cta, g_r, nullptr, g_Bf1b, nullptr,
                                      P.P2[9], nullptr, 0, g_q,
                                      g_sum2, g_sq2, nullptr);
    grid_bar(++gen);

    // ---- P9: Bf2 = diag(s2)@f2w2 tiles ; bias3 ----
    if (cta < 16) {
        split_tile_sc(smem, P.P2[12], g_Bf2, g_sum2, g_sq2, P.P2[10], cta);
    } else if (cta == 16) {
        const float inv_n = 1.f / (float)N_NODES;
        int n = threadIdx.x;
        float s = P.P2[13][n];
        for (int k = 0; k < 256; k++) {
            float mu = __ldcg(g_sum2 + k) * inv_n;
            float var = __ldcg(g_sq2 + k) * inv_n - mu * mu;
            float rs = rsqrtf(var + BN_EPS);
            s += (P.P2[11][k] - mu * rs * P.P2[10][k]) * P.P2[12][(k << 8) + n];
        }
        g_bias3[n] = s;
    }
    grid_bar(++gen);

    // ---- P10: out[:,0:256] = (q2*s2+t2)@f2w2 + f2b2 ; out[:,256:512] = x ----
    gemm_phase<3, true, false, true>(smem, cta, g_q, nullptr, g_Bf2, nullptr,
                                     g_bias3, P.out, 512, nullptr,
                                     nullptr, nullptr, P.x);
}

// ================= host orchestration ========================================
extern "C" void kernel_launch(void* const* d_in, const int* in_sizes, int n_in,
                              void* d_out, int out_size) {
    (void)in_sizes; (void)n_in; (void)out_size;

    Params P;
    P.x  = (const float*)d_in[0];
    P.ei = (const int*)d_in[2];
    for (int i = 0; i < 14; i++) {
        P.P1[i] = (const float*)d_in[4 + i];
        P.P2[i] = (const float*)d_in[18 + i];
    }
    P.out = (float*)d_out;

    cudaFuncSetAttribute(mega_k, cudaFuncAttributeMaxDynamicSharedMemorySize,
                         SMEM_MMA);

    mega_k<<<256, 256, SMEM_MMA>>>(P);
}

// round 15
// speedup vs baseline: 1.2408x; 1.0541x over previous
#include <cuda_runtime.h>
#include <cuda_fp16.h>

#define N_NODES 16384
#define N_EDGES 262144
#define D_CH    256
#define BN_EPS  1e-5f

// ================= device scratch (no runtime allocation) ==================
__device__ __half g_x [N_NODES * D_CH];
__device__ __half g_e [N_NODES * D_CH];
__device__ __half g_e2[N_NODES * D_CH];
__device__ __half g_r [N_NODES * D_CH];
__device__ __half g_q [N_NODES * D_CH];

__device__ __half g_ew1h[N_NODES * D_CH];
__device__ __half g_ew2h[N_NODES * D_CH];

// stacked split weights, [N=256 rows][K'=512]: [hi(256) | lo(256)]
__device__ __half g_Bw1a[D_CH * 512];
__device__ __half g_Bf1a[D_CH * 512];
__device__ __half g_Bw1b[D_CH * 512];
__device__ __half g_Bf1b[D_CH * 512];
__device__ __half g_Bwx [D_CH * 512];
__device__ __half g_B2  [D_CH * 512];
__device__ __half g_Bf2 [D_CH * 512];

__device__ float g_wx1[D_CH * D_CH];
__device__ float g_wx2[D_CH * D_CH];
__device__ float g_G  [D_CH * D_CH];

__device__ float g_biasr[D_CH];
__device__ float g_bias3[D_CH];

__device__ float g_sum1[D_CH];
__device__ float g_sq1 [D_CH];
__device__ float g_sum2[D_CH];
__device__ float g_sq2 [D_CH];

__device__ int g_deg[N_NODES];       // zeroed at end of each run (scatter phase)
__device__ int g_off[N_NODES + 1];
__device__ int g_cur[N_NODES];
__device__ int g_csr[N_EDGES];

__device__ unsigned g_flags[256];    // grid barrier flags (monotone gens)
__device__ unsigned g_pair [256];    // pair barrier flags (monotone gens)

// ================= PTX helpers ==============================================
__device__ __forceinline__ unsigned smem_u32(const void* p) {
    unsigned a;
    asm("{ .reg .u64 t; cvta.to.shared.u64 t, %1; cvt.u32.u64 %0, t; }"
        : "=r"(a) : "l"(p));
    return a;
}
__device__ __forceinline__ void cp16(unsigned dst, const void* src) {
    asm volatile("cp.async.cg.shared.global [%0], [%1], 16;"
                 :: "r"(dst), "l"(src) : "memory");
}
__device__ __forceinline__ void cp_commit() {
    asm volatile("cp.async.commit_group;" ::: "memory");
}
template <int N>
__device__ __forceinline__ void cp_wait() {
    asm volatile("cp.async.wait_group %0;" :: "n"(N) : "memory");
}
__device__ __forceinline__ void ldsm_x4(unsigned* r, unsigned addr) {
    asm volatile("ldmatrix.sync.aligned.m8n8.x4.shared.b16 {%0,%1,%2,%3}, [%4];"
                 : "=r"(r[0]), "=r"(r[1]), "=r"(r[2]), "=r"(r[3]) : "r"(addr));
}
__device__ __forceinline__ void mma_fp16(float* c, const unsigned* a, const unsigned* b) {
    asm volatile(
        "mma.sync.aligned.m16n8k16.row.col.f32.f16.f16.f32 "
        "{%0,%1,%2,%3}, {%4,%5,%6,%7}, {%8,%9}, {%0,%1,%2,%3};"
        : "+f"(c[0]), "+f"(c[1]), "+f"(c[2]), "+f"(c[3])
        : "r"(a[0]), "r"(a[1]), "r"(a[2]), "r"(a[3]), "r"(b[0]), "r"(b[1]));
}
__device__ __forceinline__ void split1h(float v, __half& h, __half& l) {
    h = __float2half_rn(v);
    l = __float2half_rn(v - __half2float(h));
}
__device__ __forceinline__ uint2 pack4h(float4 v) {
    __half2 a = __floats2half2_rn(v.x, v.y);
    __half2 b = __floats2half2_rn(v.z, v.w);
    uint2 r;
    r.x = *(unsigned*)&a;
    r.y = *(unsigned*)&b;
    return r;
}

// ================= barriers ==================================================
__device__ __forceinline__ void grid_bar(unsigned gen) {
    __syncthreads();
    __threadfence();
    if (threadIdx.x == 0) atomicExch(&g_flags[blockIdx.x], gen);
    for (;;) {
        unsigned v = __ldcg(&g_flags[threadIdx.x]);
        if (__syncthreads_and((int)(v - gen) >= 0)) break;
        __nanosleep(128);
    }
    __threadfence();
}

// pair barrier: CTA syncs only with partner (blockIdx.x ^ 1).
// Downstream consumers of pair-synced data use cp.async.cg (L2 path), so
// L2-level visibility via __threadfence is sufficient.
__device__ __forceinline__ void pair_bar(unsigned gen) {
    __syncthreads();
    __threadfence();
    if (threadIdx.x == 0) {
        atomicExch(&g_pair[blockIdx.x], gen);
        while ((int)(__ldcg(&g_pair[blockIdx.x ^ 1]) - gen) < 0) __nanosleep(64);
    }
    __syncthreads();
}

// ================= phase pieces ==============================================
__device__ void conv_unit(unsigned u, const float* x, const float* ew1,
                          const float* ew2) {
    if (u < 4096) {
        int i = u * 256 + threadIdx.x;
        ((uint2*)g_x)[i] = pack4h(((const float4*)x)[i]);
    } else if (u < 8192) {
        int i = (u - 4096) * 256 + threadIdx.x;
        ((uint2*)g_ew1h)[i] = pack4h(((const float4*)ew1)[i]);
    } else if (u < 12288) {
        int i = (u - 8192) * 256 + threadIdx.x;
        ((uint2*)g_ew2h)[i] = pack4h(((const float4*)ew2)[i]);
    } else {
        int j = threadIdx.x;
        g_sum1[j] = 0.f; g_sq1[j] = 0.f;
        g_sum2[j] = 0.f; g_sq2[j] = 0.f;
    }
}

template <bool ADD_A>
__device__ __noinline__ void wx_tile(char* sm, const float* A, const float* B,
                                     float* Cf, int bm, int bn) {
    float* As = (float*)sm;
    float* Bs = As + 16 * 64;
    int tx = threadIdx.x & 15, ty = threadIdx.x >> 4;
    int r = threadIdx.x >> 2, c4 = (threadIdx.x & 3) * 4;
    int rb = threadIdx.x >> 4, cb = (threadIdx.x & 15) * 4;
    float acc[4][4] = {};
    float4 av = *(const float4*)(A + (bm + r) * 256 + c4);
    float4 bv = *(const float4*)(B + rb * 256 + bn + cb);
    for (int kt = 0; kt < 256; kt += 16) {
        As[(c4 + 0) * 64 + r] = av.x; As[(c4 + 1) * 64 + r] = av.y;
        As[(c4 + 2) * 64 + r] = av.z; As[(c4 + 3) * 64 + r] = av.w;
        *(float4*)&Bs[rb * 68 + cb] = bv;
        __syncthreads();
        if (kt < 240) {
            av = *(const float4*)(A + (bm + r) * 256 + kt + 16 + c4);
            bv = *(const float4*)(B + (kt + 16 + rb) * 256 + bn + cb);
        }
#pragma unroll
        for (int k = 0; k < 16; k++) {
            float a[4], b[4];
#pragma unroll
            for (int i = 0; i < 4; i++) a[i] = As[k * 64 + ty * 4 + i];
#pragma unroll
            for (int j = 0; j < 4; j++) b[j] = Bs[k * 68 + tx * 4 + j];
#pragma unroll
            for (int i = 0; i < 4; i++)
#pragma unroll
                for (int j = 0; j < 4; j++) acc[i][j] = fmaf(a[i], b[j], acc[i][j]);
        }
        __syncthreads();
    }
#pragma unroll
    for (int i = 0; i < 4; i++) {
        int k = bm + ty * 4 + i;
#pragma unroll
        for (int j = 0; j < 4; j++)
            Cf[k * 256 + bn + tx * 4 + j] = acc[i][j] + (ADD_A ? A[k * 256 + bn + tx * 4 + j] : 0.f);
    }
    __syncthreads();
}

__device__ __noinline__ void split_tile(char* sm, const float* W, __half* Bo,
                                        bool addI, int t) {
    float* T = (float*)sm;
    int kt = (t & 3) * 64, nt = (t >> 2) * 64;
    int r4 = threadIdx.x >> 6, c = threadIdx.x & 63;
#pragma unroll
    for (int i = 0; i < 16; i++) {
        int row = i * 4 + r4;
        float w = W[(kt + row) * 256 + nt + c];
        if (addI && (kt + row) == (nt + c)) w += 1.f;
        T[row * 65 + c] = w;
    }
    __syncthreads();
#pragma unroll
    for (int i = 0; i < 16; i++) {
        int nl = i * 4 + r4;
        __half h, l;
        split1h(T[c * 65 + nl], h, l);
        Bo[(nt + nl) * 512 + kt + c]       = h;
        Bo[(nt + nl) * 512 + 256 + kt + c] = l;
    }
    __syncthreads();
}

__device__ __noinline__ void split_tile_sc(char* sm, const float* W, __half* Bo,
                                           const float* sums, const float* sqs,
                                           const float* gamma, int t) {
    const float inv_n = 1.f / (float)N_NODES;
    float* T = (float*)sm;
    float* sc = T + 64 * 65;
    int kt = (t & 3) * 64, nt = (t >> 2) * 64;
    if (threadIdx.x < 64) {
        int k = kt + threadIdx.x;
        float mu = __ldcg(sums + k) * inv_n;
        float var = __ldcg(sqs + k) * inv_n - mu * mu;
        sc[threadIdx.x] = rsqrtf(var + BN_EPS) * gamma[k];
    }
    __syncthreads();
    int r4 = threadIdx.x >> 6, c = threadIdx.x & 63;
#pragma unroll
    for (int i = 0; i < 16; i++) {
        int row = i * 4 + r4;
        T[row * 65 + c] = sc[row] * W[(kt + row) * 256 + nt + c];
    }
    __syncthreads();
#pragma unroll
    for (int i = 0; i < 16; i++) {
        int nl = i * 4 + r4;
        __half h, l;
        split1h(T[c * 65 + nl], h, l);
        Bo[(nt + nl) * 512 + kt + c]       = h;
        Bo[(nt + nl) * 512 + 256 + kt + c] = l;
    }
    __syncthreads();
}

__device__ __noinline__ void scan256(char* sm) {
    int* sd = (int*)sm;
    int* ps = sd + 16384;
    int t = threadIdx.x;
    for (int i = t; i < N_NODES; i += 256) sd[i] = g_deg[i];
    __syncthreads();
    int base = t * 64;
    int sum = 0;
#pragma unroll 8
    for (int i = 0; i < 64; i++) sum += sd[base + i];
    ps[t] = sum;
    __syncthreads();
    for (int d = 1; d < 256; d <<= 1) {
        int v = (t >= d) ? ps[t - d] : 0;
        __syncthreads();
        if (t >= d) ps[t] += v;
        __syncthreads();
    }
    int run = (t == 0) ? 0 : ps[t - 1];
#pragma unroll 8
    for (int i = 0; i < 64; i++) {
        int v = sd[base + i];
        g_off[base + i] = run;
        g_cur[base + i] = run;
        run += v;
    }
    if (t == 255) g_off[N_NODES] = run;
    __syncthreads();
}

// merged spmm: one CSR traversal, both layers. u in [0,4096)
__device__ void spmm_unit2(int u, const float* eb1, const float* eb2) {
    int node = u * 4 + (threadIdx.x >> 6);
    int c = threadIdx.x & 63;
    const uint2* w1 = (const uint2*)g_ew1h;
    const uint2* w2 = (const uint2*)g_ew2h;
    float4 a1 = ((const float4*)eb1)[c];
    float4 a2 = ((const float4*)eb2)[c];
    int s = g_off[node];
    int e = g_off[node + 1];
    for (int k = s; k < e; k++) {
        int j = g_csr[k] * 64 + c;
        uint2 v1 = w1[j];
        uint2 v2 = w2[j];
        float2 p0 = __half22float2(*(const __half2*)&v1.x);
        float2 p1 = __half22float2(*(const __half2*)&v1.y);
        a1.x += p0.x; a1.y += p0.y; a1.z += p1.x; a1.w += p1.y;
        float2 q0 = __half22float2(*(const __half2*)&v2.x);
        float2 q1 = __half22float2(*(const __half2*)&v2.y);
        a2.x += q0.x; a2.y += q0.y; a2.z += q1.x; a2.w += q1.y;
    }
    ((uint2*)g_e)[node * 64 + c]  = pack4h(a1);
    ((uint2*)g_e2)[node * 64 + c] = pack4h(a2);
}

// ================= HMMA fp16 2-term GEMM phase ==============================
#define STAGES   3
#define BUF_SZ   32768
#define STATS_OFF (STAGES * BUF_SZ)
#define SMEM_MMA (STATS_OFF + 1024)

template <int MODE, bool F32S, bool HST, bool XCOPY>
__device__ __noinline__ void gemm_phase(char* smem, int cta,
        const __half* A, const __half* A2,
        const __half* Bb, const __half* B2b,
        const float* bias,
        float* outf, int ldout, __half* oh,
        float* sumP, float* sqP, const float* xsrc) {
    const unsigned sbase = smem_u32(smem);
    const int tid = threadIdx.x;
    const int lane = tid & 31;
    const int w = tid >> 5;
    const int wm = w & 3;
    const int wn = w >> 2;
    const int bm = (cta >> 1) * 128;
    const int bn = (cta & 1) * 128;

    const int NC = (MODE == 1) ? 16 : 8;

    auto issue = [&](int c) {
        const bool second = (MODE == 1) && (c >= 8);
        const int local = second ? c - 8 : c;
        const __half* Ap = second ? A2 : A;
        const __half* Bp = second ? B2b : Bb;
        const int ka = (local & 3) << 6;
        const int kb = local << 6;
        const unsigned sa = sbase + (c % STAGES) * BUF_SZ;
        const unsigned sb = sa + 16384;
#pragma unroll
        for (int i = 0; i < 4; i++) {
            int u = tid + (i << 8);
            int row = u >> 3, seg = u & 7;
            cp16(sa + row * 128 + ((seg ^ (row & 7)) << 4),
                 Ap + ((bm + row) << 8) + ka + (seg << 3));
        }
#pragma unroll
        for (int i = 0; i < 4; i++) {
            int u = tid + (i << 8);
            int row = u >> 3, seg = u & 7;
            cp16(sb + row * 128 + ((seg ^ (row & 7)) << 4),
                 Bp + (bn + row) * 512 + kb + (seg << 3));
        }
        cp_commit();
    };

    const int a_row = wm * 32 + (lane & 15);
    const int a_kh = lane >> 4;
    const int b_nrel = ((lane >> 4) << 3) + (lane & 7);
    const int b_n = wn * 64 + b_nrel;
    const int b_kh = (lane >> 3) & 1;

    float acc[2][8][4];
#pragma unroll
    for (int mt = 0; mt < 2; mt++)
#pragma unroll
        for (int nt = 0; nt < 8; nt++)
#pragma unroll
            for (int q = 0; q < 4; q++) acc[mt][nt][q] = 0.f;

    issue(0); issue(1); issue(2);

    for (int c = 0; c < NC; c++) {
        if (c >= NC - 2) cp_wait<0>(); else cp_wait<STAGES - 1>();
        __syncthreads();
        const unsigned sa = sbase + (c % STAGES) * BUF_SZ;
        const unsigned sb = sa + 16384;
#pragma unroll
        for (int ks = 0; ks < 4; ks++) {
            const int seg0 = ks * 2;
            unsigned af[2][4];
#pragma unroll
            for (int mt = 0; mt < 2; mt++) {
                int r = a_row + mt * 16;
                ldsm_x4(af[mt], sa + r * 128 + (((seg0 + a_kh) ^ (r & 7)) << 4));
            }
            unsigned bf[8][2];
#pragma unroll
            for (int np = 0; np < 4; np++) {
                int n = b_n + np * 16;
                unsigned t4[4];
                ldsm_x4(t4, sb + n * 128 + (((seg0 + b_kh) ^ (n & 7)) << 4));
                bf[np * 2][0] = t4[0]; bf[np * 2][1] = t4[1];
                bf[np * 2 + 1][0] = t4[2]; bf[np * 2 + 1][1] = t4[3];
            }
#pragma unroll
            for (int mt = 0; mt < 2; mt++)
#pragma unroll
                for (int nt = 0; nt < 8; nt++)
                    mma_fp16(acc[mt][nt], af[mt], bf[nt]);
        }
        __syncthreads();
        if (c + STAGES < NC) issue(c + STAGES);
    }
    __syncthreads();

    const int er = lane >> 2;
    const int ec = (lane & 3) << 1;
#pragma unroll
    for (int mt = 0; mt < 2; mt++) {
#pragma unroll
        for (int nt = 0; nt < 8; nt++) {
            int r0 = wm * 32 + mt * 16 + er;
            int cc = wn * 64 + nt * 8 + ec;
            float b0 = __ldcg(bias + bn + cc), b1 = __ldcg(bias + bn + cc + 1);
            float v0 = acc[mt][nt][0] + b0, v1 = acc[mt][nt][1] + b1;
            float v2 = acc[mt][nt][2] + b0, v3 = acc[mt][nt][3] + b1;
            if (MODE == 1 || MODE == 2) {
                v0 = fmaxf(v0, 0.f); v1 = fmaxf(v1, 0.f);
                v2 = fmaxf(v2, 0.f); v3 = fmaxf(v3, 0.f);
            }
            int r1 = r0 + 8;
            *(float2*)(smem + r0 * 512 + ((((cc >> 2) ^ ((r0 & 7) << 2))) << 4) + ((cc & 3) << 2)) = make_float2(v0, v1);
            *(float2*)(smem + r1 * 512 + ((((cc >> 2) ^ ((r1 & 7) << 2))) << 4) + ((cc & 3) << 2)) = make_float2(v2, v3);
        }
    }
    __syncthreads();

#pragma unroll 4
    for (int i = 0; i < 16; i++) {
        int u = tid + (i << 8);
        int r = u >> 5, seg = u & 31;
        float4 v = *(const float4*)(smem + r * 512 + ((seg ^ ((r & 7) << 2)) << 4));
        int grow = bm + r;
        int gcol = bn + (seg << 2);
        if (F32S) {
            *(float4*)(outf + grow * ldout + gcol) = v;
            if (XCOPY) {
                float4 xv = ((const float4*)xsrc)[(grow << 6) + (gcol >> 2)];
                *(float4*)(outf + grow * ldout + 256 + gcol) = xv;
            }
        }
        if (HST)  ((uint2*)oh)[(grow << 6) + (gcol >> 2)] = pack4h(v);
    }

    if (MODE == 2) {
        int c = tid & 127, r0 = (tid >> 7) << 6;
        float s = 0.f, q = 0.f;
#pragma unroll 4
        for (int rr = 0; rr < 64; rr++) {
            int r = r0 + rr;
            float v = *(const float*)(smem + r * 512 +
                                      ((((c >> 2) ^ ((r & 7) << 2))) << 4) + ((c & 3) << 2));
            s += v;
            q += v * v;
        }
        float* st = (float*)(smem + STATS_OFF);
        __syncthreads();
        if (tid >= 128) { st[c] = s; st[128 + c] = q; }
        __syncthreads();
        if (tid < 128) {
            atomicAdd(&sumP[bn + c], s + st[c]);
            atomicAdd(&sqP [bn + c], q + st[128 + c]);
        }
    }
    __syncthreads();
}

// ================= the mega kernel ==========================================
struct Params {
    const float* x;
    const int* ei;
    const float* P1[14];
    const float* P2[14];
    float* out;
};

__global__ __launch_bounds__(256, 2) void mega_k(Params P) {
    extern __shared__ char smem[];
    const int cta = blockIdx.x;
    unsigned gen = __ldcg(&g_flags[cta]);

    // ---- P0: conversions (all CTAs) + wx tiles + hist + biasr1 ----
    if (cta < 16) {
        wx_tile<true>(smem, P.P2[2], P.P2[6], g_wx2, (cta >> 2) * 64, (cta & 3) * 64);
    } else if (cta < 32) {
        wx_tile<true>(smem, P.P1[2], P.P1[6], g_wx1, ((cta - 16) >> 2) * 64, ((cta - 16) & 3) * 64);
    } else if (cta == 32) {
        int n = threadIdx.x;
        float s = P.P1[5][n] + P.P1[7][n] + P.P1[3][n];
        for (int k = 0; k < 256; k++) s += P.P1[3][k] * P.P1[6][k * 256 + n];
        g_biasr[n] = s;
    } else if (cta < 97) {
        for (int u = cta - 33; u < 1024; u += 64) {
            int e = u * 256 + threadIdx.x;
            atomicAdd(&g_deg[P.ei[N_EDGES + e]], 1);
        }
    }
    for (unsigned u = cta; u < 12289u; u += 256)
        conv_unit(u, P.x, P.P1[0], P.P2[0]);
    grid_bar(++gen);

    // ---- P1: scan (CTA 0) || G tiles || splitw tiles ----
    if (cta == 0) {
        scan256(smem);
    } else if (cta < 17) {
        wx_tile<false>(smem, P.P1[12], g_wx2, g_G, ((cta - 1) >> 2) * 64, ((cta - 1) & 3) * 64);
    } else if (cta < 97) {
        int b = cta - 17;
        int mat = b >> 4, t = b & 15;
        const float* W;
        __half* B;
        bool addI = false;
        switch (mat) {
            case 0: W = P.P1[4]; B = g_Bw1a; addI = true; break;
            case 1: W = P.P1[8]; B = g_Bf1a; break;
            case 2: W = P.P2[4]; B = g_Bw1b; addI = true; break;
            case 3: W = P.P2[8]; B = g_Bf1b; break;
            default: W = g_wx1;  B = g_Bwx; break;
        }
        split_tile(smem, W, B, addI, t);
    }
    grid_bar(++gen);

    // ---- P2: scatter + zero g_deg for next run ----
    for (int u = cta; u < 1024; u += 256) {
        int e = u * 256 + threadIdx.x;
        int d = P.ei[N_EDGES + e];
        int p = atomicAdd(&g_cur[d], 1);
        g_csr[p] = P.ei[e];
    }
    if (cta < 64) g_deg[cta * 256 + threadIdx.x] = 0;
    grid_bar(++gen);

    // ---- P3: merged spmm, pair-local rows (pair rb owns nodes rb*128..+128)
    {
        int u0 = (cta >> 1) * 32 + (cta & 1) * 16;
        for (int u = u0; u < u0 + 16; u++)
            spmm_unit2(u, P.P1[1], P.P2[1]);
    }
    pair_bar(++gen);

    // ---- P4: r1 = relu(emb1@(I+c1w1) + x@wx1 + biasr1) ----
    gemm_phase<1, false, true, false>(smem, cta, g_e, g_x, g_Bw1a, g_Bwx,
                                      g_biasr, nullptr, 0, g_r,
                                      nullptr, nullptr, nullptr);
    pair_bar(++gen);

    // ---- P5: q1 = relu(r1@f1w1 + f1b1), stats1 ----
    gemm_phase<2, false, true, false>(smem, cta, g_r, nullptr, g_Bf1a, nullptr,
                                      P.P1[9], nullptr, 0, g_q,
                                      g_sum1, g_sq1, nullptr);
    grid_bar(++gen);

    // ---- P6: B2 = diag(s1)@G tiles ; biasr = layer2 fused bias ----
    if (cta < 16) {
        split_tile_sc(smem, g_G, g_B2, g_sum1, g_sq1, P.P1[10], cta);
    } else if (cta == 16) {
        const float inv_n = 1.f / (float)N_NODES;
        int n = threadIdx.x;
        float s = P.P2[5][n] + P.P2[7][n] + P.P2[3][n];
        for (int k = 0; k < 256; k++) {
            float mu = __ldcg(g_sum1 + k) * inv_n;
            float var = __ldcg(g_sq1 + k) * inv_n - mu * mu;
            float rs = rsqrtf(var + BN_EPS);
            float t1 = P.P1[11][k] - mu * rs * P.P1[10][k];
            s += P.P2[3][k] * P.P2[6][k * 256 + n] + t1 * g_G[(k << 8) + n]
               + P.P1[13][k] * g_wx2[(k << 8) + n];
        }
        g_biasr[n] = s;
    }
    grid_bar(++gen);

    // ---- P7: r2 = relu(emb2@(I+c1w2) + q1@B2 + biasr2) ----
    gemm_phase<1, false, true, false>(smem, cta, g_e2, g_q, g_Bw1b, g_B2,
                                      g_biasr, nullptr, 0, g_r,
                                      nullptr, nullptr, nullptr);
    pair_bar(++gen);

    // ---- P8: q2 = relu(r2@f1w2 + f1b2), stats2 ----
    gemm_phase<2, false, true, false>(smem, cta, g_r, nullptr, g_Bf1b, nullptr,
                                      P.P2[9], nullptr, 0, g_q,
                                      g_sum2, g_sq2, nullptr);
    grid_bar(++gen);

    // ---- P9: Bf2 = diag(s2)@f2w2 tiles ; bias3 ----
    if (cta < 16) {
        split_tile_sc(smem, P.P2[12], g_Bf2, g_sum2, g_sq2, P.P2[10], cta);
    } else if (cta == 16) {
        const float inv_n = 1.f / (float)N_NODES;
        int n = threadIdx.x;
        float s = P.P2[13][n];
        for (int k = 0; k < 256; k++) {
            float mu = __ldcg(g_sum2 + k) * inv_n;
            float var = __ldcg(g_sq2 + k) * inv_n - mu * mu;
            float rs = rsqrtf(var + BN_EPS);
            s += (P.P2[11][k] - mu * rs * P.P2[10][k]) * P.P2[12][(k << 8) + n];
        }
        g_bias3[n] = s;
    }
    grid_bar(++gen);

    // ---- P10: out[:,0:256] = (q2*s2+t2)@f2w2 + f2b2 ; out[:,256:512] = x ----
    gemm_phase<3, true, false, true>(smem, cta, g_q, nullptr, g_Bf2, nullptr,
                                     g_bias3, P.out, 512, nullptr,
                                     nullptr, nullptr, P.x);
}

// ================= host orchestration ========================================
extern "C" void kernel_launch(void* const* d_in, const int* in_sizes, int n_in,
                              void* d_out, int out_size) {
    (void)in_sizes; (void)n_in; (void)out_size;

    Params P;
    P.x  = (const float*)d_in[0];
    P.ei = (const int*)d_in[2];
    for (int i = 0; i < 14; i++) {
        P.P1[i] = (const float*)d_in[4 + i];
        P.P2[i] = (const float*)d_in[18 + i];
    }
    P.out = (float*)d_out;

    cudaFuncSetAttribute(mega_k, cudaFuncAttributeMaxDynamicSharedMemorySize,
                         SMEM_MMA);

    mega_k<<<256, 256, SMEM_MMA>>>(P);
}